// round 10
// baseline (speedup 1.0000x reference)
#include <cuda_runtime.h>
#include <math.h>
#include <stdint.h>

#define EDGES 40000
#define ATOMS 2000
#define F 64
#define NLM 25
#define EF ((size_t)EDGES * F)

// ============================================================================
// Compile-time real Clebsch-Gordan table (replicates reference exactly)
// ============================================================================
namespace cgbuild {

constexpr double cfact(int n){ double r=1.0; for(int i=2;i<=n;++i) r*=(double)i; return r; }
constexpr double csqrt(double v){
  if(v<=0.0) return 0.0;
  double x = v>1.0 ? v : 1.0;
  for(int i=0;i<64;++i) x = 0.5*(x + v/x);
  return x;
}
constexpr double cabsd(double v){ return v<0.0 ? -v : v; }

constexpr double cg_complex(int l1,int m1,int l2,int m2,int l3,int m3){
  if(m3 != m1+m2) return 0.0;
  int lmin = l1>l2 ? l1-l2 : l2-l1;
  if(l3 < lmin || l3 > l1+l2) return 0.0;
  double pre = (2.0*l3+1.0)*cfact(l1+l2-l3)*cfact(l1-l2+l3)*cfact(-l1+l2+l3)/cfact(l1+l2+l3+1);
  pre = csqrt(pre*cfact(l1+m1)*cfact(l1-m1)*cfact(l2+m2)*cfact(l2-m2)*cfact(l3+m3)*cfact(l3-m3));
  double s = 0.0;
  for(int k=0;k<=l1+l2-l3;++k){
    int d2=l1-m1-k, d3=l2+m2-k, d4=l3-l2+m1+k, d5=l3-l1-m2+k;
    if(d2<0||d3<0||d4<0||d5<0) continue;
    double den = cfact(k)*cfact(l1+l2-l3-k)*cfact(d2)*cfact(d3)*cfact(d4)*cfact(d5);
    s += ((k&1) ? -1.0 : 1.0)/den;
  }
  return pre*s;
}

struct CD { double re, im; };
constexpr CD cmul(CD a, CD b){ return CD{a.re*b.re - a.im*b.im, a.re*b.im + a.im*b.re}; }

constexpr double INV_SQRT2 = 0.70710678118654752440;

struct URow { int n; int m[2]; CD c[2]; };
constexpr URow urow(int l, int a){
  URow r{};
  int m = a - l;
  double s = INV_SQRT2;
  if(m==0){ r.n=1; r.m[0]=0; r.c[0]=CD{1.0,0.0}; return r; }
  if(m>0){
    r.n=2;
    r.m[0]=m;  r.c[0]=CD{ ((m&1)? -1.0:1.0)*s, 0.0};
    r.m[1]=-m; r.c[1]=CD{ s, 0.0};
    return r;
  }
  int am = -m;
  r.n=2;
  r.m[0]=m;  r.c[0]=CD{0.0, s};
  r.m[1]=am; r.c[1]=CD{0.0, -(((am&1)? -1.0:1.0))*s};
  return r;
}

constexpr int MAXE = 4608;
struct Ent { int i1,i2,i3; float c; };
struct CGTab {
  Ent e[MAXE];
  int pstart[43];
  int pl3[42];
  int n; int npaths; bool overflow;
};

constexpr CGTab build_cg(){
  CGTab T{};
  int p = 0;
  for(int l1=0;l1<=4;++l1)
  for(int l2=0;l2<=4;++l2){
    int lmin = l1>l2 ? l1-l2 : l2-l1;
    int lcap = (l1+l2 < 4) ? (l1+l2) : 4;
    for(int l3=lmin; l3<=lcap; ++l3){
      if(((l1+l2+l3)&1) != 0) continue;
      T.pstart[p] = T.n;
      T.pl3[p] = l3;
      for(int a=0;a<2*l1+1;++a)
      for(int b=0;b<2*l2+1;++b){
        double acc[9]={0,0,0,0,0,0,0,0,0};
        URow u1 = urow(l1,a);
        URow u2 = urow(l2,b);
        for(int t1=0;t1<u1.n;++t1)
        for(int t2=0;t2<u2.n;++t2){
          int m3 = u1.m[t1]+u2.m[t2];
          if(m3 > l3 || m3 < -l3) continue;
          double cc = cg_complex(l1,u1.m[t1],l2,u2.m[t2],l3,m3);
          if(cc==0.0) continue;
          CD c12 = cmul(u1.c[t1], u2.c[t2]);
          c12.re *= cc; c12.im *= cc;
          int rows[2] = { m3, -m3 };
          int nr = (m3==0) ? 1 : 2;
          for(int rr=0;rr<nr;++rr){
            int cidx = rows[rr] + l3;
            URow u3 = urow(l3, cidx);
            for(int t3=0;t3<u3.n;++t3){
              if(u3.m[t3]==m3){
                acc[cidx] += c12.re*u3.c[t3].re + c12.im*u3.c[t3].im;
              }
            }
          }
        }
        for(int c_=0;c_<2*l3+1;++c_){
          if(cabsd(acc[c_]) > 1e-10){
            if(T.n >= MAXE){ T.overflow = true; }
            else {
              T.e[T.n].i1 = l1*l1 + a;
              T.e[T.n].i2 = l2*l2 + b;
              T.e[T.n].i3 = l3*l3 + c_;
              T.e[T.n].c  = (float)acc[c_];
              T.n++;
            }
          }
        }
      }
      ++p;
    }
  }
  T.pstart[p] = T.n;
  T.npaths = p;
  return T;
}

constexpr CGTab CG = build_cg();
static_assert(!CG.overflow, "cg table overflow");
static_assert(CG.npaths == 42, "path count must be 42");
static_assert(CG.n > 0, "cg table empty");

} // namespace cgbuild

// ============================================================================
// Scratch (device globals: sanctioned no-alloc workaround)
// ============================================================================
__device__ float g_y[NLM*(size_t)EDGES*F];
__device__ float g_u[NLM*(size_t)EDGES*F];
__device__ float g_v[NLM*(size_t)EDGES*F];
__device__ float g_t[NLM*(size_t)EDGES*F];
__device__ float g_a[(size_t)ATOMS*F];

__constant__ int DEGC[NLM] = {0,1,1,1,2,2,2,2,2,3,3,3,3,3,3,3,4,4,4,4,4,4,4,4,4};

// ============================================================================
// Kernel 1: per-atom embedding a = emb[Z] @ W_emb_t ; init d_out
// ============================================================================
__global__ void __launch_bounds__(256) k_atom_emb(
    const int* __restrict__ Z, const float* __restrict__ emb,
    const float* __restrict__ Wt, float* __restrict__ a, float* __restrict__ out)
{
  int t = blockIdx.x*256 + threadIdx.x;
  if(t >= ATOMS*F) return;
  int n = t>>6, f = t&63;
  int z = Z[n];
  const float* er = emb + (size_t)z*F;
  float s = 0.f;
  #pragma unroll
  for(int k=0;k<F;++k) s = fmaf(er[k], Wt[k*F+f], s);
  a[t] = s;
  float* orow = out + (size_t)n*NLM*F + f;
  orow[0] = s;
  #pragma unroll
  for(int lm=1;lm<NLM;++lm) orow[(size_t)lm*F] = 0.f;
}

// ============================================================================
// Kernel 2: edge features y[lm][e][f] = SH(unit)[lm] * rad[f]
// ============================================================================
__global__ void __launch_bounds__(256) k_edge_y(
    const int* __restrict__ nbr, const float* __restrict__ disp,
    const int* __restrict__ Z, const float* __restrict__ Wrad,
    float* __restrict__ y)
{
  int t = blockIdx.x*256 + threadIdx.x;
  int e = t>>6, f = t&63;
  if(e >= EDGES) return;
  int j  = nbr[2*e+1];
  int zj = Z[j];
  float dx = disp[3*e+0], dy = disp[3*e+1], dz = disp[3*e+2];
  float r = sqrtf(dx*dx + dy*dy + dz*dz + 1e-12f);
  float inv = 1.0f / r;
  float x = dx*inv, yy = dy*inv, z = dz*inv;
  float fc = 0.f;
  if(r < 5.0f) fc = 0.5f*(cosf(3.14159265358979323846f * r / 5.0f) + 1.0f);

  const float* wr = Wrad + (size_t)zj*16*F + f;
  float rad = 0.f;
  #pragma unroll
  for(int k=0;k<16;++k){
    float d = r - (float)k*(5.0f/15.0f);
    float g = expf(-10.24f*d*d)*fc;
    rad = fmaf(g, wr[(size_t)k*F], rad);
  }

  float x2=x*x, y2=yy*yy, z2=z*z;
  float sh[NLM];
  sh[0]=0.28209479177387814f;
  sh[1]=0.4886025119029199f*yy;
  sh[2]=0.4886025119029199f*z;
  sh[3]=0.4886025119029199f*x;
  sh[4]=1.0925484305920792f*x*yy;
  sh[5]=1.0925484305920792f*yy*z;
  sh[6]=0.31539156525252005f*(3.f*z2-1.f);
  sh[7]=1.0925484305920792f*x*z;
  sh[8]=0.5462742152960396f*(x2-y2);
  sh[9]=0.5900435899266435f*yy*(3.f*x2-y2);
  sh[10]=2.890611442640554f*x*yy*z;
  sh[11]=0.4570457994644658f*yy*(5.f*z2-1.f);
  sh[12]=0.3731763325901154f*z*(5.f*z2-3.f);
  sh[13]=0.4570457994644658f*x*(5.f*z2-1.f);
  sh[14]=1.445305721320277f*z*(x2-y2);
  sh[15]=0.5900435899266435f*x*(x2-3.f*y2);
  sh[16]=2.5033429417967046f*x*yy*(x2-y2);
  sh[17]=1.7701307697799304f*yy*z*(3.f*x2-y2);
  sh[18]=0.9461746957575601f*x*yy*(7.f*z2-1.f);
  sh[19]=0.6690465435572892f*yy*z*(7.f*z2-3.f);
  sh[20]=0.10578554691520431f*(35.f*z2*z2-30.f*z2+3.f);
  sh[21]=0.6690465435572892f*x*z*(7.f*z2-3.f);
  sh[22]=0.47308734787878004f*(x2-y2)*(7.f*z2-1.f);
  sh[23]=1.7701307697799304f*x*z*(x2-3.f*y2);
  sh[24]=0.6258357354491761f*(x2*x2-6.f*x2*y2+y2*y2);

  float* ye = y + (size_t)e*F + f;
  #pragma unroll
  for(int lm=0;lm<NLM;++lm) ye[(size_t)lm*EF] = sh[lm]*rad;
}

// ============================================================================
// Kernel 3a: FUSED dual GEMM: u = src @ W1[deg], v = src @ W2[deg].
// BM=128, BN=128 (u cols 0..63 | v cols 64..127), 128 threads, 8x16 per thread.
// A tile transposed+swizzled in smem (R8 pattern). 64KB dynamic smem.
// ============================================================================
__global__ void __launch_bounds__(128) k_gemm_uv(
    const float* __restrict__ src, const float* __restrict__ W1,
    const float* __restrict__ W2, float* __restrict__ dstU,
    float* __restrict__ dstV)
{
  extern __shared__ float S[];
  float* AsT = S;            // [k][row^swz] 64*128
  float* Bs  = S + 64*128;   // [k][n] 64*128 (W1 | W2)

  const int lm = blockIdx.y;
  const int e0 = blockIdx.x * 128;
  const float* A  = src + (size_t)lm*EF;
  const float* B1 = W1 + (size_t)DEGC[lm]*F*F;
  const float* B2 = W2 + (size_t)DEGC[lm]*F*F;
  const int tid = threadIdx.x;

  #pragma unroll
  for(int i=0;i<8;++i){             // each W: 1024 float4, 8 per thread
    int idx = tid + 128*i;
    int k = idx >> 4, c4 = idx & 15;
    *reinterpret_cast<float4*>(&Bs[k*128 + c4*4])      = reinterpret_cast<const float4*>(B1)[idx];
    *reinterpret_cast<float4*>(&Bs[k*128 + 64 + c4*4]) = reinterpret_cast<const float4*>(B2)[idx];
  }
  #pragma unroll
  for(int i=0;i<16;++i){            // A tile 128x64 = 2048 float4
    int idx = tid + 128*i;
    int row = idx >> 4, c4 = idx & 15;
    float4 v = make_float4(0.f,0.f,0.f,0.f);
    if(e0 + row < EDGES) v = reinterpret_cast<const float4*>(A + (size_t)(e0+row)*F)[c4];
    int xr = row ^ ((c4 & 3) * 8);
    AsT[(c4*4+0)*128 + xr] = v.x;
    AsT[(c4*4+1)*128 + xr] = v.y;
    AsT[(c4*4+2)*128 + xr] = v.z;
    AsT[(c4*4+3)*128 + xr] = v.w;
  }
  __syncthreads();

  const int rowg = tid >> 3;   // 0..15, 8 rows each
  const int colg = tid & 7;    // 0..7, 16 cols each
  float acc[8][16];
  #pragma unroll
  for(int i=0;i<8;++i)
    #pragma unroll
    for(int j=0;j<16;++j) acc[i][j] = 0.f;

  #pragma unroll 4
  for(int k=0;k<64;++k){
    int xk = ((k>>2)&3)*8;
    int abase = k*128 + ((rowg*8) ^ xk);
    float4 a0 = *reinterpret_cast<const float4*>(&AsT[abase]);
    float4 a1 = *reinterpret_cast<const float4*>(&AsT[abase+4]);
    const float* brow = &Bs[k*128 + colg*16];
    float4 b0 = *reinterpret_cast<const float4*>(brow);
    float4 b1 = *reinterpret_cast<const float4*>(brow+4);
    float4 b2 = *reinterpret_cast<const float4*>(brow+8);
    float4 b3 = *reinterpret_cast<const float4*>(brow+12);
    float a[8] = {a0.x,a0.y,a0.z,a0.w,a1.x,a1.y,a1.z,a1.w};
    float b[16] = {b0.x,b0.y,b0.z,b0.w,b1.x,b1.y,b1.z,b1.w,
                   b2.x,b2.y,b2.z,b2.w,b3.x,b3.y,b3.z,b3.w};
    #pragma unroll
    for(int i=0;i<8;++i)
      #pragma unroll
      for(int j=0;j<16;++j)
        acc[i][j] = fmaf(a[i], b[j], acc[i][j]);
  }

  float* D = ((colg < 4) ? dstU : dstV) + (size_t)lm*EF;
  const int cb = (colg & 3) * 16;
  #pragma unroll
  for(int i=0;i<8;++i){
    int row = e0 + rowg*8 + i;
    if(row < EDGES){
      float* cr = D + (size_t)row*F + cb;
      *reinterpret_cast<float4*>(cr+0)  = make_float4(acc[i][0], acc[i][1], acc[i][2], acc[i][3]);
      *reinterpret_cast<float4*>(cr+4)  = make_float4(acc[i][4], acc[i][5], acc[i][6], acc[i][7]);
      *reinterpret_cast<float4*>(cr+8)  = make_float4(acc[i][8], acc[i][9], acc[i][10],acc[i][11]);
      *reinterpret_cast<float4*>(cr+12) = make_float4(acc[i][12],acc[i][13],acc[i][14],acc[i][15]);
    }
  }
}

// ============================================================================
// Kernel 3b: single GEMM: dst = src @ W[deg].
// BM=128, BN=64, 64 threads, 8x16 per thread. 48KB static smem (exact cap).
// ============================================================================
__global__ void __launch_bounds__(64) k_gemm1(
    const float* __restrict__ src, const float* __restrict__ W,
    float* __restrict__ dst)
{
  __shared__ float AsT[64*128];   // 32KB
  __shared__ float Bs[64*64];     // 16KB

  const int lm = blockIdx.y;
  const int e0 = blockIdx.x * 128;
  const float* A = src + (size_t)lm*EF;
  float*       C = dst + (size_t)lm*EF;
  const float* B = W + (size_t)DEGC[lm]*F*F;
  const int tid = threadIdx.x;

  #pragma unroll
  for(int i=0;i<16;++i){            // B: 1024 float4, 16 per thread
    int idx = tid + 64*i;
    *reinterpret_cast<float4*>(&Bs[idx*4]) = reinterpret_cast<const float4*>(B)[idx];
  }
  #pragma unroll
  for(int i=0;i<32;++i){            // A tile: 2048 float4, 32 per thread
    int idx = tid + 64*i;
    int row = idx >> 4, c4 = idx & 15;
    float4 v = make_float4(0.f,0.f,0.f,0.f);
    if(e0 + row < EDGES) v = reinterpret_cast<const float4*>(A + (size_t)(e0+row)*F)[c4];
    int xr = row ^ ((c4 & 3) * 8);
    AsT[(c4*4+0)*128 + xr] = v.x;
    AsT[(c4*4+1)*128 + xr] = v.y;
    AsT[(c4*4+2)*128 + xr] = v.z;
    AsT[(c4*4+3)*128 + xr] = v.w;
  }
  __syncthreads();

  const int rowg = tid >> 2;   // 0..15, 8 rows each
  const int colg = tid & 3;    // 0..3, 16 cols each
  float acc[8][16];
  #pragma unroll
  for(int i=0;i<8;++i)
    #pragma unroll
    for(int j=0;j<16;++j) acc[i][j] = 0.f;

  #pragma unroll 4
  for(int k=0;k<64;++k){
    int xk = ((k>>2)&3)*8;
    int abase = k*128 + ((rowg*8) ^ xk);
    float4 a0 = *reinterpret_cast<const float4*>(&AsT[abase]);
    float4 a1 = *reinterpret_cast<const float4*>(&AsT[abase+4]);
    const float* brow = &Bs[k*64 + colg*16];
    float4 b0 = *reinterpret_cast<const float4*>(brow);
    float4 b1 = *reinterpret_cast<const float4*>(brow+4);
    float4 b2 = *reinterpret_cast<const float4*>(brow+8);
    float4 b3 = *reinterpret_cast<const float4*>(brow+12);
    float a[8] = {a0.x,a0.y,a0.z,a0.w,a1.x,a1.y,a1.z,a1.w};
    float b[16] = {b0.x,b0.y,b0.z,b0.w,b1.x,b1.y,b1.z,b1.w,
                   b2.x,b2.y,b2.z,b2.w,b3.x,b3.y,b3.z,b3.w};
    #pragma unroll
    for(int i=0;i<8;++i)
      #pragma unroll
      for(int j=0;j<16;++j)
        acc[i][j] = fmaf(a[i], b[j], acc[i][j]);
  }

  const int cb = colg * 16;
  #pragma unroll
  for(int i=0;i<8;++i){
    int row = e0 + rowg*8 + i;
    if(row < EDGES){
      float* cr = C + (size_t)row*F + cb;
      *reinterpret_cast<float4*>(cr+0)  = make_float4(acc[i][0], acc[i][1], acc[i][2], acc[i][3]);
      *reinterpret_cast<float4*>(cr+4)  = make_float4(acc[i][4], acc[i][5], acc[i][6], acc[i][7]);
      *reinterpret_cast<float4*>(cr+8)  = make_float4(acc[i][8], acc[i][9], acc[i][10],acc[i][11]);
      *reinterpret_cast<float4*>(cr+12) = make_float4(acc[i][12],acc[i][13],acc[i][14],acc[i][15]);
    }
  }
}

// ============================================================================
// Kernel 4: CG tensor product, template-unrolled with literal indices.
// ============================================================================
template<int Lo, int Hi, int L3SQ>
__device__ __forceinline__ void ent_run(const float* __restrict__ u,
                                        const float* __restrict__ v,
                                        float* __restrict__ praw)
{
  if constexpr (Hi - Lo == 1) {
    constexpr int i1 = cgbuild::CG.e[Lo].i1;
    constexpr int i2 = cgbuild::CG.e[Lo].i2;
    constexpr int i3 = cgbuild::CG.e[Lo].i3 - L3SQ;
    constexpr float c = cgbuild::CG.e[Lo].c;
    praw[i3] = fmaf(u[i1]*v[i2], c, praw[i3]);
  } else if constexpr (Hi > Lo) {
    constexpr int Mid = Lo + (Hi - Lo)/2;
    ent_run<Lo, Mid, L3SQ>(u, v, praw);
    ent_run<Mid, Hi, L3SQ>(u, v, praw);
  }
}

template<int P>
__device__ __forceinline__ void path_run(const float* __restrict__ u,
                                         const float* __restrict__ v,
                                         float* __restrict__ t,
                                         const float* __restrict__ wp, int f)
{
  if constexpr (P < 42) {
    constexpr int l3 = cgbuild::CG.pl3[P];
    constexpr int s  = cgbuild::CG.pstart[P];
    constexpr int e  = cgbuild::CG.pstart[P+1];
    float wpf = wp[P*64 + f];
    float praw[2*l3+1];
    #pragma unroll
    for(int c=0;c<2*l3+1;++c) praw[c] = 0.f;
    ent_run<s, e, l3*l3>(u, v, praw);
    #pragma unroll
    for(int c=0;c<2*l3+1;++c)
      t[l3*l3+c] = fmaf(praw[c], wpf, t[l3*l3+c]);
    path_run<P+1>(u, v, t, wp, f);
  }
}

__global__ void __launch_bounds__(128) k_cg(
    const float* __restrict__ u_, const float* __restrict__ v_,
    const float* __restrict__ wp, float* __restrict__ t_)
{
  int t = blockIdx.x*128 + threadIdx.x;
  if(t >= EDGES*F) return;
  int f = t & 63;

  float u[NLM], v[NLM], tacc[NLM];
  #pragma unroll
  for(int lm=0;lm<NLM;++lm){
    u[lm] = u_[(size_t)lm*EF + t];
    v[lm] = v_[(size_t)lm*EF + t];
    tacc[lm] = 0.f;
  }

  path_run<0>(u, v, tacc, wp, f);

  #pragma unroll
  for(int lm=0;lm<NLM;++lm) t_[(size_t)lm*EF + t] = tacc[lm];
}

// ============================================================================
// Kernel 5: scale + scatter-add to atoms
// ============================================================================
__global__ void __launch_bounds__(256) k_scatter(
    const float* __restrict__ y, const float* __restrict__ a,
    const int* __restrict__ nbr, const float* __restrict__ twt,
    float* __restrict__ out)
{
  int t = blockIdx.x*256 + threadIdx.x;
  int e = t>>6, f = t&63;
  if(e >= EDGES) return;
  int i = nbr[2*e];
  float af = a[(size_t)i*F + f];
  float* orow = out + (size_t)i*NLM*F + f;
  #pragma unroll
  for(int lm=0;lm<NLM;++lm){
    float val = y[(size_t)lm*EF + t] * af * twt[DEGC[lm]*F + f];
    atomicAdd(&orow[(size_t)lm*F], val);
  }
}

// ============================================================================
// Launch
// ============================================================================
extern "C" void kernel_launch(void* const* d_in, const int* in_sizes, int n_in,
                              void* d_out, int out_size)
{
  const int*   Z     = (const int*)  d_in[0];
  const int*   nbr   = (const int*)  d_in[1];
  const float* disp  = (const float*)d_in[2];
  const float* emb   = (const float*)d_in[3];
  const float* Wembt = (const float*)d_in[4];
  const float* Wrad  = (const float*)d_in[5];
  const float* W1[2] = { (const float*)d_in[6],  (const float*)d_in[10] };
  const float* W2[2] = { (const float*)d_in[7],  (const float*)d_in[11] };
  const float* wp[2] = { (const float*)d_in[8],  (const float*)d_in[12] };
  const float* Wo[2] = { (const float*)d_in[9],  (const float*)d_in[13] };
  const float* twt   = (const float*)d_in[14];
  float* out = (float*)d_out;

  float *y, *u, *v, *t, *a;
  cudaGetSymbolAddress((void**)&y, g_y);
  cudaGetSymbolAddress((void**)&u, g_u);
  cudaGetSymbolAddress((void**)&v, g_v);
  cudaGetSymbolAddress((void**)&t, g_t);
  cudaGetSymbolAddress((void**)&a, g_a);

  const int SMEM_UV = 64*128*4 * 2;   // 64KB dynamic
  cudaFuncSetAttribute(k_gemm_uv, cudaFuncAttributeMaxDynamicSharedMemorySize, SMEM_UV);

  k_atom_emb<<<(ATOMS*F + 255)/256, 256>>>(Z, emb, Wembt, a, out);
  k_edge_y<<<(EDGES*F + 255)/256, 256>>>(nbr, disp, Z, Wrad, y);

  dim3 gg((EDGES + 127)/128, NLM);
  for(int L=0; L<2; ++L){
    k_gemm_uv<<<gg, 128, SMEM_UV>>>(y, W1[L], W2[L], u, v);
    k_cg<<<(EDGES*F + 127)/128, 128>>>(u, v, wp[L], t);
    k_gemm1<<<gg, 64>>>(t, Wo[L], y);
  }

  k_scatter<<<(EDGES*F + 255)/256, 256>>>(y, a, nbr, twt, out);
}

// round 11
// speedup vs baseline: 1.1961x; 1.1961x over previous
#include <cuda_runtime.h>
#include <math.h>
#include <stdint.h>

#define EDGES 40000
#define ATOMS 2000
#define F 64
#define NLM 25
#define EF ((size_t)EDGES * F)

// ============================================================================
// Compile-time real Clebsch-Gordan table (replicates reference exactly)
// ============================================================================
namespace cgbuild {

constexpr double cfact(int n){ double r=1.0; for(int i=2;i<=n;++i) r*=(double)i; return r; }
constexpr double csqrt(double v){
  if(v<=0.0) return 0.0;
  double x = v>1.0 ? v : 1.0;
  for(int i=0;i<64;++i) x = 0.5*(x + v/x);
  return x;
}
constexpr double cabsd(double v){ return v<0.0 ? -v : v; }

constexpr double cg_complex(int l1,int m1,int l2,int m2,int l3,int m3){
  if(m3 != m1+m2) return 0.0;
  int lmin = l1>l2 ? l1-l2 : l2-l1;
  if(l3 < lmin || l3 > l1+l2) return 0.0;
  double pre = (2.0*l3+1.0)*cfact(l1+l2-l3)*cfact(l1-l2+l3)*cfact(-l1+l2+l3)/cfact(l1+l2+l3+1);
  pre = csqrt(pre*cfact(l1+m1)*cfact(l1-m1)*cfact(l2+m2)*cfact(l2-m2)*cfact(l3+m3)*cfact(l3-m3));
  double s = 0.0;
  for(int k=0;k<=l1+l2-l3;++k){
    int d2=l1-m1-k, d3=l2+m2-k, d4=l3-l2+m1+k, d5=l3-l1-m2+k;
    if(d2<0||d3<0||d4<0||d5<0) continue;
    double den = cfact(k)*cfact(l1+l2-l3-k)*cfact(d2)*cfact(d3)*cfact(d4)*cfact(d5);
    s += ((k&1) ? -1.0 : 1.0)/den;
  }
  return pre*s;
}

struct CD { double re, im; };
constexpr CD cmul(CD a, CD b){ return CD{a.re*b.re - a.im*b.im, a.re*b.im + a.im*b.re}; }

constexpr double INV_SQRT2 = 0.70710678118654752440;

struct URow { int n; int m[2]; CD c[2]; };
constexpr URow urow(int l, int a){
  URow r{};
  int m = a - l;
  double s = INV_SQRT2;
  if(m==0){ r.n=1; r.m[0]=0; r.c[0]=CD{1.0,0.0}; return r; }
  if(m>0){
    r.n=2;
    r.m[0]=m;  r.c[0]=CD{ ((m&1)? -1.0:1.0)*s, 0.0};
    r.m[1]=-m; r.c[1]=CD{ s, 0.0};
    return r;
  }
  int am = -m;
  r.n=2;
  r.m[0]=m;  r.c[0]=CD{0.0, s};
  r.m[1]=am; r.c[1]=CD{0.0, -(((am&1)? -1.0:1.0))*s};
  return r;
}

constexpr int MAXE = 4608;
struct Ent { int i1,i2,i3; float c; };
struct CGTab {
  Ent e[MAXE];
  int pstart[43];
  int pl3[42];
  int n; int npaths; bool overflow;
};

constexpr CGTab build_cg(){
  CGTab T{};
  int p = 0;
  for(int l1=0;l1<=4;++l1)
  for(int l2=0;l2<=4;++l2){
    int lmin = l1>l2 ? l1-l2 : l2-l1;
    int lcap = (l1+l2 < 4) ? (l1+l2) : 4;
    for(int l3=lmin; l3<=lcap; ++l3){
      if(((l1+l2+l3)&1) != 0) continue;
      T.pstart[p] = T.n;
      T.pl3[p] = l3;
      for(int a=0;a<2*l1+1;++a)
      for(int b=0;b<2*l2+1;++b){
        double acc[9]={0,0,0,0,0,0,0,0,0};
        URow u1 = urow(l1,a);
        URow u2 = urow(l2,b);
        for(int t1=0;t1<u1.n;++t1)
        for(int t2=0;t2<u2.n;++t2){
          int m3 = u1.m[t1]+u2.m[t2];
          if(m3 > l3 || m3 < -l3) continue;
          double cc = cg_complex(l1,u1.m[t1],l2,u2.m[t2],l3,m3);
          if(cc==0.0) continue;
          CD c12 = cmul(u1.c[t1], u2.c[t2]);
          c12.re *= cc; c12.im *= cc;
          int rows[2] = { m3, -m3 };
          int nr = (m3==0) ? 1 : 2;
          for(int rr=0;rr<nr;++rr){
            int cidx = rows[rr] + l3;
            URow u3 = urow(l3, cidx);
            for(int t3=0;t3<u3.n;++t3){
              if(u3.m[t3]==m3){
                acc[cidx] += c12.re*u3.c[t3].re + c12.im*u3.c[t3].im;
              }
            }
          }
        }
        for(int c_=0;c_<2*l3+1;++c_){
          if(cabsd(acc[c_]) > 1e-10){
            if(T.n >= MAXE){ T.overflow = true; }
            else {
              T.e[T.n].i1 = l1*l1 + a;
              T.e[T.n].i2 = l2*l2 + b;
              T.e[T.n].i3 = l3*l3 + c_;
              T.e[T.n].c  = (float)acc[c_];
              T.n++;
            }
          }
        }
      }
      ++p;
    }
  }
  T.pstart[p] = T.n;
  T.npaths = p;
  return T;
}

constexpr CGTab CG = build_cg();
static_assert(!CG.overflow, "cg table overflow");
static_assert(CG.npaths == 42, "path count must be 42");
static_assert(CG.n > 0, "cg table empty");

} // namespace cgbuild

// ============================================================================
// Scratch (device globals: sanctioned no-alloc workaround)
// ============================================================================
__device__ float g_y[NLM*(size_t)EDGES*F];
__device__ float g_u[NLM*(size_t)EDGES*F];
__device__ float g_v[NLM*(size_t)EDGES*F];
__device__ float g_t[NLM*(size_t)EDGES*F];
__device__ float g_a[(size_t)ATOMS*F];

__constant__ int DEGC[NLM] = {0,1,1,1,2,2,2,2,2,3,3,3,3,3,3,3,4,4,4,4,4,4,4,4,4};

// ============================================================================
// Kernel 1: per-atom embedding a = emb[Z] @ W_emb_t ; init d_out
// ============================================================================
__global__ void __launch_bounds__(256) k_atom_emb(
    const int* __restrict__ Z, const float* __restrict__ emb,
    const float* __restrict__ Wt, float* __restrict__ a, float* __restrict__ out)
{
  int t = blockIdx.x*256 + threadIdx.x;
  if(t >= ATOMS*F) return;
  int n = t>>6, f = t&63;
  int z = Z[n];
  const float* er = emb + (size_t)z*F;
  float s = 0.f;
  #pragma unroll
  for(int k=0;k<F;++k) s = fmaf(er[k], Wt[k*F+f], s);
  a[t] = s;
  float* orow = out + (size_t)n*NLM*F + f;
  orow[0] = s;
  #pragma unroll
  for(int lm=1;lm<NLM;++lm) orow[(size_t)lm*F] = 0.f;
}

// ============================================================================
// Kernel 2: edge features y[lm][e][f] = SH(unit)[lm] * rad[f]
// ============================================================================
__global__ void __launch_bounds__(256) k_edge_y(
    const int* __restrict__ nbr, const float* __restrict__ disp,
    const int* __restrict__ Z, const float* __restrict__ Wrad,
    float* __restrict__ y)
{
  int t = blockIdx.x*256 + threadIdx.x;
  int e = t>>6, f = t&63;
  if(e >= EDGES) return;
  int j  = nbr[2*e+1];
  int zj = Z[j];
  float dx = disp[3*e+0], dy = disp[3*e+1], dz = disp[3*e+2];
  float r = sqrtf(dx*dx + dy*dy + dz*dz + 1e-12f);
  float inv = 1.0f / r;
  float x = dx*inv, yy = dy*inv, z = dz*inv;
  float fc = 0.f;
  if(r < 5.0f) fc = 0.5f*(cosf(3.14159265358979323846f * r / 5.0f) + 1.0f);

  const float* wr = Wrad + (size_t)zj*16*F + f;
  float rad = 0.f;
  #pragma unroll
  for(int k=0;k<16;++k){
    float d = r - (float)k*(5.0f/15.0f);
    float g = expf(-10.24f*d*d)*fc;
    rad = fmaf(g, wr[(size_t)k*F], rad);
  }

  float x2=x*x, y2=yy*yy, z2=z*z;
  float sh[NLM];
  sh[0]=0.28209479177387814f;
  sh[1]=0.4886025119029199f*yy;
  sh[2]=0.4886025119029199f*z;
  sh[3]=0.4886025119029199f*x;
  sh[4]=1.0925484305920792f*x*yy;
  sh[5]=1.0925484305920792f*yy*z;
  sh[6]=0.31539156525252005f*(3.f*z2-1.f);
  sh[7]=1.0925484305920792f*x*z;
  sh[8]=0.5462742152960396f*(x2-y2);
  sh[9]=0.5900435899266435f*yy*(3.f*x2-y2);
  sh[10]=2.890611442640554f*x*yy*z;
  sh[11]=0.4570457994644658f*yy*(5.f*z2-1.f);
  sh[12]=0.3731763325901154f*z*(5.f*z2-3.f);
  sh[13]=0.4570457994644658f*x*(5.f*z2-1.f);
  sh[14]=1.445305721320277f*z*(x2-y2);
  sh[15]=0.5900435899266435f*x*(x2-3.f*y2);
  sh[16]=2.5033429417967046f*x*yy*(x2-y2);
  sh[17]=1.7701307697799304f*yy*z*(3.f*x2-y2);
  sh[18]=0.9461746957575601f*x*yy*(7.f*z2-1.f);
  sh[19]=0.6690465435572892f*yy*z*(7.f*z2-3.f);
  sh[20]=0.10578554691520431f*(35.f*z2*z2-30.f*z2+3.f);
  sh[21]=0.6690465435572892f*x*z*(7.f*z2-3.f);
  sh[22]=0.47308734787878004f*(x2-y2)*(7.f*z2-1.f);
  sh[23]=1.7701307697799304f*x*z*(x2-3.f*y2);
  sh[24]=0.6258357354491761f*(x2*x2-6.f*x2*y2+y2*y2);

  float* ye = y + (size_t)e*F + f;
  #pragma unroll
  for(int lm=0;lm<NLM;++lm) ye[(size_t)lm*EF] = sh[lm]*rad;
}

// ============================================================================
// Kernel 3a: FUSED dual GEMM: u = src@W1[deg], v = src@W2[deg].
// BM=128, BN=128 (u cols 0..63 | v cols 64..127), 128 threads, 8x16/thread.
// A: transposed+XOR-swizzled (R8 pattern, proven conflict-free reads).
// B: j-interleaved layout -> column c at k*128 + ((c>>2)&3)*32 + (c>>4)*4 + (c&3)
//    so each b_j LDS.128 (lanes colg=0..7 at j*32+colg*4) spans banks 0..31.
// smem 64KB dynamic.
// ============================================================================
__global__ void __launch_bounds__(128) k_gemm_uv(
    const float* __restrict__ src, const float* __restrict__ W1,
    const float* __restrict__ W2, float* __restrict__ dstU,
    float* __restrict__ dstV)
{
  extern __shared__ float S[];
  float* AsT = S;            // 64*128 floats: [k][row^swz]
  float* Bs  = S + 64*128;   // 64*128 floats: j-interleaved (u|v)

  const int lm = blockIdx.y;
  const int e0 = blockIdx.x * 128;
  const float* A  = src + (size_t)lm*EF;
  const float* B1 = W1 + (size_t)DEGC[lm]*F*F;
  const float* B2 = W2 + (size_t)DEGC[lm]*F*F;
  const int tid = threadIdx.x;

  #pragma unroll
  for(int i=0;i<8;++i){             // each W: 1024 float4, 8 per thread
    int idx = tid + 128*i;
    int k = idx >> 4, c4 = idx & 15;      // cols c4*4..c4*4+3 ; j=c4&3, colg=c4>>2
    int sl = k*128 + (c4&3)*32 + (c4>>2)*4;
    *reinterpret_cast<float4*>(&Bs[sl])      = reinterpret_cast<const float4*>(B1)[idx];
    *reinterpret_cast<float4*>(&Bs[sl + 16]) = reinterpret_cast<const float4*>(B2)[idx]; // colg+4
  }
  #pragma unroll
  for(int i=0;i<16;++i){            // A tile 128x64 = 2048 float4
    int idx = tid + 128*i;
    int row = idx >> 4, c4 = idx & 15;
    float4 v = make_float4(0.f,0.f,0.f,0.f);
    if(e0 + row < EDGES) v = reinterpret_cast<const float4*>(A + (size_t)(e0+row)*F)[c4];
    int xr = row ^ ((c4 & 3) * 8);
    AsT[(c4*4+0)*128 + xr] = v.x;
    AsT[(c4*4+1)*128 + xr] = v.y;
    AsT[(c4*4+2)*128 + xr] = v.z;
    AsT[(c4*4+3)*128 + xr] = v.w;
  }
  __syncthreads();

  const int rowg = tid >> 3;   // 0..15, 8 rows each
  const int colg = tid & 7;    // 0..7, 16 cols each (0..3 -> u, 4..7 -> v)
  float acc[8][16];
  #pragma unroll
  for(int i=0;i<8;++i)
    #pragma unroll
    for(int j=0;j<16;++j) acc[i][j] = 0.f;

  #pragma unroll 4
  for(int k=0;k<64;++k){
    int xk = ((k>>2)&3)*8;
    int abase = k*128 + ((rowg*8) ^ xk);
    float4 a0 = *reinterpret_cast<const float4*>(&AsT[abase]);
    float4 a1 = *reinterpret_cast<const float4*>(&AsT[abase+4]);
    const float* brow = &Bs[k*128 + colg*4];
    float4 b0 = *reinterpret_cast<const float4*>(brow);        // j=0 -> cols +0..3
    float4 b1 = *reinterpret_cast<const float4*>(brow+32);     // j=1 -> cols +4..7
    float4 b2 = *reinterpret_cast<const float4*>(brow+64);     // j=2 -> cols +8..11
    float4 b3 = *reinterpret_cast<const float4*>(brow+96);     // j=3 -> cols +12..15
    float a[8] = {a0.x,a0.y,a0.z,a0.w,a1.x,a1.y,a1.z,a1.w};
    float b[16] = {b0.x,b0.y,b0.z,b0.w,b1.x,b1.y,b1.z,b1.w,
                   b2.x,b2.y,b2.z,b2.w,b3.x,b3.y,b3.z,b3.w};
    #pragma unroll
    for(int i=0;i<8;++i)
      #pragma unroll
      for(int j=0;j<16;++j)
        acc[i][j] = fmaf(a[i], b[j], acc[i][j]);
  }

  // acc[i][j*4+w] = col group colg: local col = (colg&3)*16 + j*4 + w
  float* D = ((colg < 4) ? dstU : dstV) + (size_t)lm*EF;
  const int cb = (colg & 3) * 16;
  #pragma unroll
  for(int i=0;i<8;++i){
    int row = e0 + rowg*8 + i;
    if(row < EDGES){
      float* cr = D + (size_t)row*F + cb;
      *reinterpret_cast<float4*>(cr+0)  = make_float4(acc[i][0], acc[i][1], acc[i][2], acc[i][3]);
      *reinterpret_cast<float4*>(cr+4)  = make_float4(acc[i][4], acc[i][5], acc[i][6], acc[i][7]);
      *reinterpret_cast<float4*>(cr+8)  = make_float4(acc[i][8], acc[i][9], acc[i][10],acc[i][11]);
      *reinterpret_cast<float4*>(cr+12) = make_float4(acc[i][12],acc[i][13],acc[i][14],acc[i][15]);
    }
  }
}

// ============================================================================
// Kernel 3b: single GEMM (R8 proven, 233us): dst = src @ W[deg].
// BM=128, BN=64, 128 threads, 8x8 per thread, 48KB static smem.
// ============================================================================
__global__ void __launch_bounds__(128) k_deg_dense(
    const float* __restrict__ src, const float* __restrict__ W,
    float* __restrict__ dst)
{
  __shared__ float AsT[64*128];  // [k][row^swz]
  __shared__ float Bs[64*64];

  const int lm = blockIdx.y;
  const int e0 = blockIdx.x * 128;
  const float* A = src + (size_t)lm*EF;
  float*       C = dst + (size_t)lm*EF;
  const float* B = W + (size_t)DEGC[lm]*F*F;
  const int tid = threadIdx.x;

  {
    const float4* B4 = reinterpret_cast<const float4*>(B);
    float4* Bs4 = reinterpret_cast<float4*>(Bs);
    #pragma unroll
    for(int i=0;i<8;++i) Bs4[tid + 128*i] = B4[tid + 128*i];
  }
  #pragma unroll
  for(int i=0;i<16;++i){
    int idx = tid + 128*i;
    int row = idx >> 4, c4 = idx & 15;
    float4 v = make_float4(0.f,0.f,0.f,0.f);
    if(e0 + row < EDGES) v = reinterpret_cast<const float4*>(A + (size_t)(e0+row)*F)[c4];
    int xr = row ^ ((c4 & 3) * 8);
    AsT[(c4*4+0)*128 + xr] = v.x;
    AsT[(c4*4+1)*128 + xr] = v.y;
    AsT[(c4*4+2)*128 + xr] = v.z;
    AsT[(c4*4+3)*128 + xr] = v.w;
  }
  __syncthreads();

  const int mt = tid >> 3;
  const int nt = tid & 7;
  float acc[8][8];
  #pragma unroll
  for(int i=0;i<8;++i)
    #pragma unroll
    for(int j=0;j<8;++j) acc[i][j] = 0.f;

  #pragma unroll 4
  for(int k=0;k<64;++k){
    int xk = ((k>>2)&3)*8;
    int base = k*128 + ((mt*8) ^ xk);
    float4 a0 = *reinterpret_cast<const float4*>(&AsT[base]);
    float4 a1 = *reinterpret_cast<const float4*>(&AsT[base+4]);
    float4 b0 = *reinterpret_cast<const float4*>(&Bs[k*64 + nt*8]);
    float4 b1 = *reinterpret_cast<const float4*>(&Bs[k*64 + nt*8+4]);
    float a[8] = {a0.x,a0.y,a0.z,a0.w,a1.x,a1.y,a1.z,a1.w};
    float b[8] = {b0.x,b0.y,b0.z,b0.w,b1.x,b1.y,b1.z,b1.w};
    #pragma unroll
    for(int i=0;i<8;++i)
      #pragma unroll
      for(int j=0;j<8;++j)
        acc[i][j] = fmaf(a[i], b[j], acc[i][j]);
  }

  #pragma unroll
  for(int i=0;i<8;++i){
    int row = e0 + mt*8 + i;
    if(row < EDGES){
      float4 v0 = make_float4(acc[i][0],acc[i][1],acc[i][2],acc[i][3]);
      float4 v1 = make_float4(acc[i][4],acc[i][5],acc[i][6],acc[i][7]);
      float4* crow = reinterpret_cast<float4*>(C + (size_t)row*F + nt*8);
      crow[0] = v0; crow[1] = v1;
    }
  }
}

// ============================================================================
// Kernel 4: CG tensor product, template-unrolled with literal indices.
// ============================================================================
template<int Lo, int Hi, int L3SQ>
__device__ __forceinline__ void ent_run(const float* __restrict__ u,
                                        const float* __restrict__ v,
                                        float* __restrict__ praw)
{
  if constexpr (Hi - Lo == 1) {
    constexpr int i1 = cgbuild::CG.e[Lo].i1;
    constexpr int i2 = cgbuild::CG.e[Lo].i2;
    constexpr int i3 = cgbuild::CG.e[Lo].i3 - L3SQ;
    constexpr float c = cgbuild::CG.e[Lo].c;
    praw[i3] = fmaf(u[i1]*v[i2], c, praw[i3]);
  } else if constexpr (Hi > Lo) {
    constexpr int Mid = Lo + (Hi - Lo)/2;
    ent_run<Lo, Mid, L3SQ>(u, v, praw);
    ent_run<Mid, Hi, L3SQ>(u, v, praw);
  }
}

template<int P>
__device__ __forceinline__ void path_run(const float* __restrict__ u,
                                         const float* __restrict__ v,
                                         float* __restrict__ t,
                                         const float* __restrict__ wp, int f)
{
  if constexpr (P < 42) {
    constexpr int l3 = cgbuild::CG.pl3[P];
    constexpr int s  = cgbuild::CG.pstart[P];
    constexpr int e  = cgbuild::CG.pstart[P+1];
    float wpf = wp[P*64 + f];
    float praw[2*l3+1];
    #pragma unroll
    for(int c=0;c<2*l3+1;++c) praw[c] = 0.f;
    ent_run<s, e, l3*l3>(u, v, praw);
    #pragma unroll
    for(int c=0;c<2*l3+1;++c)
      t[l3*l3+c] = fmaf(praw[c], wpf, t[l3*l3+c]);
    path_run<P+1>(u, v, t, wp, f);
  }
}

__global__ void __launch_bounds__(128) k_cg(
    const float* __restrict__ u_, const float* __restrict__ v_,
    const float* __restrict__ wp, float* __restrict__ t_)
{
  int t = blockIdx.x*128 + threadIdx.x;
  if(t >= EDGES*F) return;
  int f = t & 63;

  float u[NLM], v[NLM], tacc[NLM];
  #pragma unroll
  for(int lm=0;lm<NLM;++lm){
    u[lm] = u_[(size_t)lm*EF + t];
    v[lm] = v_[(size_t)lm*EF + t];
    tacc[lm] = 0.f;
  }

  path_run<0>(u, v, tacc, wp, f);

  #pragma unroll
  for(int lm=0;lm<NLM;++lm) t_[(size_t)lm*EF + t] = tacc[lm];
}

// ============================================================================
// Kernel 5: scale + scatter-add to atoms
// ============================================================================
__global__ void __launch_bounds__(256) k_scatter(
    const float* __restrict__ y, const float* __restrict__ a,
    const int* __restrict__ nbr, const float* __restrict__ twt,
    float* __restrict__ out)
{
  int t = blockIdx.x*256 + threadIdx.x;
  int e = t>>6, f = t&63;
  if(e >= EDGES) return;
  int i = nbr[2*e];
  float af = a[(size_t)i*F + f];
  float* orow = out + (size_t)i*NLM*F + f;
  #pragma unroll
  for(int lm=0;lm<NLM;++lm){
    float val = y[(size_t)lm*EF + t] * af * twt[DEGC[lm]*F + f];
    atomicAdd(&orow[(size_t)lm*F], val);
  }
}

// ============================================================================
// Launch
// ============================================================================
extern "C" void kernel_launch(void* const* d_in, const int* in_sizes, int n_in,
                              void* d_out, int out_size)
{
  const int*   Z     = (const int*)  d_in[0];
  const int*   nbr   = (const int*)  d_in[1];
  const float* disp  = (const float*)d_in[2];
  const float* emb   = (const float*)d_in[3];
  const float* Wembt = (const float*)d_in[4];
  const float* Wrad  = (const float*)d_in[5];
  const float* W1[2] = { (const float*)d_in[6],  (const float*)d_in[10] };
  const float* W2[2] = { (const float*)d_in[7],  (const float*)d_in[11] };
  const float* wp[2] = { (const float*)d_in[8],  (const float*)d_in[12] };
  const float* Wo[2] = { (const float*)d_in[9],  (const float*)d_in[13] };
  const float* twt   = (const float*)d_in[14];
  float* out = (float*)d_out;

  float *y, *u, *v, *t, *a;
  cudaGetSymbolAddress((void**)&y, g_y);
  cudaGetSymbolAddress((void**)&u, g_u);
  cudaGetSymbolAddress((void**)&v, g_v);
  cudaGetSymbolAddress((void**)&t, g_t);
  cudaGetSymbolAddress((void**)&a, g_a);

  const int SMEM_UV = 64*128*4 * 2;   // 64KB dynamic
  cudaFuncSetAttribute(k_gemm_uv, cudaFuncAttributeMaxDynamicSharedMemorySize, SMEM_UV);

  k_atom_emb<<<(ATOMS*F + 255)/256, 256>>>(Z, emb, Wembt, a, out);
  k_edge_y<<<(EDGES*F + 255)/256, 256>>>(nbr, disp, Z, Wrad, y);

  dim3 gg((EDGES + 127)/128, NLM);
  for(int L=0; L<2; ++L){
    k_gemm_uv<<<gg, 128, SMEM_UV>>>(y, W1[L], W2[L], u, v);
    k_cg<<<(EDGES*F + 127)/128, 128>>>(u, v, wp[L], t);
    k_deg_dense<<<gg, 128>>>(t, Wo[L], y);
  }

  k_scatter<<<(EDGES*F + 255)/256, 256>>>(y, a, nbr, twt, out);
}

// round 12
// speedup vs baseline: 1.6049x; 1.3418x over previous
#include <cuda_runtime.h>
#include <cuda_bf16.h>
#include <math.h>
#include <stdint.h>

#define EDGES 40000
#define ATOMS 2000
#define F 64
#define NLM 25
#define EF ((size_t)EDGES * F)

// ============================================================================
// Compile-time real Clebsch-Gordan table (replicates reference exactly)
// ============================================================================
namespace cgbuild {

constexpr double cfact(int n){ double r=1.0; for(int i=2;i<=n;++i) r*=(double)i; return r; }
constexpr double csqrt(double v){
  if(v<=0.0) return 0.0;
  double x = v>1.0 ? v : 1.0;
  for(int i=0;i<64;++i) x = 0.5*(x + v/x);
  return x;
}
constexpr double cabsd(double v){ return v<0.0 ? -v : v; }

constexpr double cg_complex(int l1,int m1,int l2,int m2,int l3,int m3){
  if(m3 != m1+m2) return 0.0;
  int lmin = l1>l2 ? l1-l2 : l2-l1;
  if(l3 < lmin || l3 > l1+l2) return 0.0;
  double pre = (2.0*l3+1.0)*cfact(l1+l2-l3)*cfact(l1-l2+l3)*cfact(-l1+l2+l3)/cfact(l1+l2+l3+1);
  pre = csqrt(pre*cfact(l1+m1)*cfact(l1-m1)*cfact(l2+m2)*cfact(l2-m2)*cfact(l3+m3)*cfact(l3-m3));
  double s = 0.0;
  for(int k=0;k<=l1+l2-l3;++k){
    int d2=l1-m1-k, d3=l2+m2-k, d4=l3-l2+m1+k, d5=l3-l1-m2+k;
    if(d2<0||d3<0||d4<0||d5<0) continue;
    double den = cfact(k)*cfact(l1+l2-l3-k)*cfact(d2)*cfact(d3)*cfact(d4)*cfact(d5);
    s += ((k&1) ? -1.0 : 1.0)/den;
  }
  return pre*s;
}

struct CD { double re, im; };
constexpr CD cmul(CD a, CD b){ return CD{a.re*b.re - a.im*b.im, a.re*b.im + a.im*b.re}; }

constexpr double INV_SQRT2 = 0.70710678118654752440;

struct URow { int n; int m[2]; CD c[2]; };
constexpr URow urow(int l, int a){
  URow r{};
  int m = a - l;
  double s = INV_SQRT2;
  if(m==0){ r.n=1; r.m[0]=0; r.c[0]=CD{1.0,0.0}; return r; }
  if(m>0){
    r.n=2;
    r.m[0]=m;  r.c[0]=CD{ ((m&1)? -1.0:1.0)*s, 0.0};
    r.m[1]=-m; r.c[1]=CD{ s, 0.0};
    return r;
  }
  int am = -m;
  r.n=2;
  r.m[0]=m;  r.c[0]=CD{0.0, s};
  r.m[1]=am; r.c[1]=CD{0.0, -(((am&1)? -1.0:1.0))*s};
  return r;
}

constexpr int MAXE = 4608;
struct Ent { int i1,i2,i3; float c; };
struct CGTab {
  Ent e[MAXE];
  int pstart[43];
  int pl3[42];
  int n; int npaths; bool overflow;
};

constexpr CGTab build_cg(){
  CGTab T{};
  int p = 0;
  for(int l1=0;l1<=4;++l1)
  for(int l2=0;l2<=4;++l2){
    int lmin = l1>l2 ? l1-l2 : l2-l1;
    int lcap = (l1+l2 < 4) ? (l1+l2) : 4;
    for(int l3=lmin; l3<=lcap; ++l3){
      if(((l1+l2+l3)&1) != 0) continue;
      T.pstart[p] = T.n;
      T.pl3[p] = l3;
      for(int a=0;a<2*l1+1;++a)
      for(int b=0;b<2*l2+1;++b){
        double acc[9]={0,0,0,0,0,0,0,0,0};
        URow u1 = urow(l1,a);
        URow u2 = urow(l2,b);
        for(int t1=0;t1<u1.n;++t1)
        for(int t2=0;t2<u2.n;++t2){
          int m3 = u1.m[t1]+u2.m[t2];
          if(m3 > l3 || m3 < -l3) continue;
          double cc = cg_complex(l1,u1.m[t1],l2,u2.m[t2],l3,m3);
          if(cc==0.0) continue;
          CD c12 = cmul(u1.c[t1], u2.c[t2]);
          c12.re *= cc; c12.im *= cc;
          int rows[2] = { m3, -m3 };
          int nr = (m3==0) ? 1 : 2;
          for(int rr=0;rr<nr;++rr){
            int cidx = rows[rr] + l3;
            URow u3 = urow(l3, cidx);
            for(int t3=0;t3<u3.n;++t3){
              if(u3.m[t3]==m3){
                acc[cidx] += c12.re*u3.c[t3].re + c12.im*u3.c[t3].im;
              }
            }
          }
        }
        for(int c_=0;c_<2*l3+1;++c_){
          if(cabsd(acc[c_]) > 1e-10){
            if(T.n >= MAXE){ T.overflow = true; }
            else {
              T.e[T.n].i1 = l1*l1 + a;
              T.e[T.n].i2 = l2*l2 + b;
              T.e[T.n].i3 = l3*l3 + c_;
              T.e[T.n].c  = (float)acc[c_];
              T.n++;
            }
          }
        }
      }
      ++p;
    }
  }
  T.pstart[p] = T.n;
  T.npaths = p;
  return T;
}

constexpr CGTab CG = build_cg();
static_assert(!CG.overflow, "cg table overflow");
static_assert(CG.npaths == 42, "path count must be 42");
static_assert(CG.n > 0, "cg table empty");

} // namespace cgbuild

// ============================================================================
// Scratch (device globals: sanctioned no-alloc workaround)
// ============================================================================
__device__ float g_y[NLM*(size_t)EDGES*F];
__device__ float g_u[NLM*(size_t)EDGES*F];
__device__ float g_v[NLM*(size_t)EDGES*F];
__device__ float g_t[NLM*(size_t)EDGES*F];
__device__ float g_a[(size_t)ATOMS*F];

__constant__ int DEGC[NLM] = {0,1,1,1,2,2,2,2,2,3,3,3,3,3,3,3,4,4,4,4,4,4,4,4,4};

// ============================================================================
// mma.sync / ldmatrix helpers (base ISA, works at compute_100 non-'a')
// ============================================================================
__device__ __forceinline__ uint32_t smem_u32(const void* p){
  uint32_t a;
  asm("{ .reg .u64 t; cvta.to.shared.u64 t, %1; cvt.u32.u64 %0, t; }" : "=r"(a) : "l"(p));
  return a;
}
__device__ __forceinline__ void ldsm_x4(uint32_t addr, uint32_t& r0, uint32_t& r1,
                                        uint32_t& r2, uint32_t& r3){
  asm volatile("ldmatrix.sync.aligned.m8n8.x4.shared.b16 {%0,%1,%2,%3}, [%4];"
    : "=r"(r0), "=r"(r1), "=r"(r2), "=r"(r3) : "r"(addr));
}
__device__ __forceinline__ void mma_bf16(float* d, const uint32_t* a, const uint32_t* b){
  asm volatile("mma.sync.aligned.m16n8k16.row.col.f32.bf16.bf16.f32 "
    "{%0,%1,%2,%3}, {%4,%5,%6,%7}, {%8,%9}, {%0,%1,%2,%3};"
    : "+f"(d[0]), "+f"(d[1]), "+f"(d[2]), "+f"(d[3])
    : "r"(a[0]), "r"(a[1]), "r"(a[2]), "r"(a[3]), "r"(b[0]), "r"(b[1]));
}

// ============================================================================
// Kernel 1: per-atom embedding a = emb[Z] @ W_emb_t ; init d_out
// ============================================================================
__global__ void __launch_bounds__(256) k_atom_emb(
    const int* __restrict__ Z, const float* __restrict__ emb,
    const float* __restrict__ Wt, float* __restrict__ a, float* __restrict__ out)
{
  int t = blockIdx.x*256 + threadIdx.x;
  if(t >= ATOMS*F) return;
  int n = t>>6, f = t&63;
  int z = Z[n];
  const float* er = emb + (size_t)z*F;
  float s = 0.f;
  #pragma unroll
  for(int k=0;k<F;++k) s = fmaf(er[k], Wt[k*F+f], s);
  a[t] = s;
  float* orow = out + (size_t)n*NLM*F + f;
  orow[0] = s;
  #pragma unroll
  for(int lm=1;lm<NLM;++lm) orow[(size_t)lm*F] = 0.f;
}

// ============================================================================
// Kernel 2: edge features y[lm][e][f] = SH(unit)[lm] * rad[f]
// ============================================================================
__global__ void __launch_bounds__(256) k_edge_y(
    const int* __restrict__ nbr, const float* __restrict__ disp,
    const int* __restrict__ Z, const float* __restrict__ Wrad,
    float* __restrict__ y)
{
  int t = blockIdx.x*256 + threadIdx.x;
  int e = t>>6, f = t&63;
  if(e >= EDGES) return;
  int j  = nbr[2*e+1];
  int zj = Z[j];
  float dx = disp[3*e+0], dy = disp[3*e+1], dz = disp[3*e+2];
  float r = sqrtf(dx*dx + dy*dy + dz*dz + 1e-12f);
  float inv = 1.0f / r;
  float x = dx*inv, yy = dy*inv, z = dz*inv;
  float fc = 0.f;
  if(r < 5.0f) fc = 0.5f*(cosf(3.14159265358979323846f * r / 5.0f) + 1.0f);

  const float* wr = Wrad + (size_t)zj*16*F + f;
  float rad = 0.f;
  #pragma unroll
  for(int k=0;k<16;++k){
    float d = r - (float)k*(5.0f/15.0f);
    float g = expf(-10.24f*d*d)*fc;
    rad = fmaf(g, wr[(size_t)k*F], rad);
  }

  float x2=x*x, y2=yy*yy, z2=z*z;
  float sh[NLM];
  sh[0]=0.28209479177387814f;
  sh[1]=0.4886025119029199f*yy;
  sh[2]=0.4886025119029199f*z;
  sh[3]=0.4886025119029199f*x;
  sh[4]=1.0925484305920792f*x*yy;
  sh[5]=1.0925484305920792f*yy*z;
  sh[6]=0.31539156525252005f*(3.f*z2-1.f);
  sh[7]=1.0925484305920792f*x*z;
  sh[8]=0.5462742152960396f*(x2-y2);
  sh[9]=0.5900435899266435f*yy*(3.f*x2-y2);
  sh[10]=2.890611442640554f*x*yy*z;
  sh[11]=0.4570457994644658f*yy*(5.f*z2-1.f);
  sh[12]=0.3731763325901154f*z*(5.f*z2-3.f);
  sh[13]=0.4570457994644658f*x*(5.f*z2-1.f);
  sh[14]=1.445305721320277f*z*(x2-y2);
  sh[15]=0.5900435899266435f*x*(x2-3.f*y2);
  sh[16]=2.5033429417967046f*x*yy*(x2-y2);
  sh[17]=1.7701307697799304f*yy*z*(3.f*x2-y2);
  sh[18]=0.9461746957575601f*x*yy*(7.f*z2-1.f);
  sh[19]=0.6690465435572892f*yy*z*(7.f*z2-3.f);
  sh[20]=0.10578554691520431f*(35.f*z2*z2-30.f*z2+3.f);
  sh[21]=0.6690465435572892f*x*z*(7.f*z2-3.f);
  sh[22]=0.47308734787878004f*(x2-y2)*(7.f*z2-1.f);
  sh[23]=1.7701307697799304f*x*z*(x2-3.f*y2);
  sh[24]=0.6258357354491761f*(x2*x2-6.f*x2*y2+y2*y2);

  float* ye = y + (size_t)e*F + f;
  #pragma unroll
  for(int lm=0;lm<NLM;++lm) ye[(size_t)lm*EF] = sh[lm]*rad;
}

// ============================================================================
// Kernel 3: tensor-core GEMM via mma.sync bf16 with 3xBF16 split.
// dst[lm] (E x 64) = src[lm] @ W[deg(lm)];  D = Ah*Bh + Ah*Bl + Al*Bh (f32 acc)
// BM=128, BN=64, K=64. 256 threads = 8 warps (2 n x 4 m), warp tile 32x32.
// smem: Ah/Al 128x64 bf16 (16KB ea), Bh/Bl 64(n)x64(k) bf16 (8KB ea) = 48KB.
// 16B chunks XOR-swizzled by (row&7) -> conflict-free ldmatrix.
// ============================================================================
__global__ void __launch_bounds__(256) k_gemm_mma(
    const float* __restrict__ src, const float* __restrict__ W,
    float* __restrict__ dst)
{
  __shared__ __nv_bfloat16 Ah[128*64], Al[128*64];   // row-major [edge][k]
  __shared__ __nv_bfloat16 Bh[64*64],  Bl[64*64];    // [n][k] (W transposed)

  const int lm = blockIdx.y;
  const int e0 = blockIdx.x * 128;
  const float* A = src + (size_t)lm*EF;
  float*       C = dst + (size_t)lm*EF;
  const float* B = W + (size_t)DEGC[lm]*F*F;
  const int tid = threadIdx.x;

  // ---- A tile: fp32 coalesced -> split hi/lo -> swizzled bf16 stores ----
  #pragma unroll
  for(int i=0;i<8;++i){
    int idx = tid + 256*i;          // 2048 float4
    int row = idx >> 4, c4 = idx & 15;
    float4 v = make_float4(0.f,0.f,0.f,0.f);
    if(e0 + row < EDGES) v = reinterpret_cast<const float4*>(A + (size_t)(e0+row)*F)[c4];
    __nv_bfloat162 h01 = __floats2bfloat162_rn(v.x, v.y);
    __nv_bfloat162 h23 = __floats2bfloat162_rn(v.z, v.w);
    __nv_bfloat162 l01 = __floats2bfloat162_rn(v.x - __bfloat162float(h01.x),
                                               v.y - __bfloat162float(h01.y));
    __nv_bfloat162 l23 = __floats2bfloat162_rn(v.z - __bfloat162float(h23.x),
                                               v.w - __bfloat162float(h23.y));
    int off = row*128 + (((c4>>1) ^ (row&7))<<4) + (c4&1)*8;
    uint2 hp, lp;
    hp.x = *reinterpret_cast<uint32_t*>(&h01); hp.y = *reinterpret_cast<uint32_t*>(&h23);
    lp.x = *reinterpret_cast<uint32_t*>(&l01); lp.y = *reinterpret_cast<uint32_t*>(&l23);
    *reinterpret_cast<uint2*>(reinterpret_cast<char*>(Ah) + off) = hp;
    *reinterpret_cast<uint2*>(reinterpret_cast<char*>(Al) + off) = lp;
  }

  // ---- B tile: W[k][n] row-major -> [n][k] transposed, split hi/lo ----
  #pragma unroll
  for(int i=0;i<4;++i){
    int idx = tid + 256*i;          // 1024 float4
    int k = idx >> 4, c4 = idx & 15;
    float4 w = reinterpret_cast<const float4*>(B)[idx];
    float vals[4] = {w.x, w.y, w.z, w.w};
    #pragma unroll
    for(int j=0;j<4;++j){
      int n = c4*4 + j;
      __nv_bfloat16 h = __float2bfloat16(vals[j]);
      __nv_bfloat16 l = __float2bfloat16(vals[j] - __bfloat162float(h));
      int off = n*128 + (((k>>3) ^ (n&7))<<4) + (k&7)*2;
      *reinterpret_cast<__nv_bfloat16*>(reinterpret_cast<char*>(Bh) + off) = h;
      *reinterpret_cast<__nv_bfloat16*>(reinterpret_cast<char*>(Bl) + off) = l;
    }
  }
  __syncthreads();

  const int wid = tid >> 5, lane = tid & 31;
  const int wm = (wid >> 1) * 32;      // 4 warps along M
  const int wn = (wid & 1) * 32;       // 2 warps along N
  const int lr = lane & 7;
  const int a_row0 = wm + lr + ((lane>>3)&1)*8;  // +mt*16
  const int a_csel = lane >> 4;                  // chunk 2kc + 0/1
  const int b_n0   = wn + lr + (lane>>4)*8;      // +np*16
  const int b_csel = (lane>>3) & 1;

  const uint32_t sAh = smem_u32(Ah), sAl = smem_u32(Al);
  const uint32_t sBh = smem_u32(Bh), sBl = smem_u32(Bl);

  float acc[2][4][4];
  #pragma unroll
  for(int mt=0;mt<2;++mt)
    #pragma unroll
    for(int nt=0;nt<4;++nt)
      #pragma unroll
      for(int q=0;q<4;++q) acc[mt][nt][q] = 0.f;

  #pragma unroll
  for(int kc=0;kc<4;++kc){
    uint32_t ah[2][4], al[2][4], bh[4][2], bl[4][2];
    #pragma unroll
    for(int mt=0;mt<2;++mt){
      int row = a_row0 + mt*16;
      uint32_t off = (uint32_t)(row*128 + (((2*kc + a_csel) ^ (row&7))<<4));
      ldsm_x4(sAh + off, ah[mt][0], ah[mt][1], ah[mt][2], ah[mt][3]);
      ldsm_x4(sAl + off, al[mt][0], al[mt][1], al[mt][2], al[mt][3]);
    }
    #pragma unroll
    for(int np=0;np<2;++np){
      int n = b_n0 + np*16;
      uint32_t off = (uint32_t)(n*128 + (((2*kc + b_csel) ^ (n&7))<<4));
      uint32_t q0,q1,q2,q3;
      ldsm_x4(sBh + off, q0,q1,q2,q3);
      bh[np*2][0]=q0; bh[np*2][1]=q1; bh[np*2+1][0]=q2; bh[np*2+1][1]=q3;
      ldsm_x4(sBl + off, q0,q1,q2,q3);
      bl[np*2][0]=q0; bl[np*2][1]=q1; bl[np*2+1][0]=q2; bl[np*2+1][1]=q3;
    }
    #pragma unroll
    for(int mt=0;mt<2;++mt)
      #pragma unroll
      for(int nt=0;nt<4;++nt){
        mma_bf16(acc[mt][nt], ah[mt], bh[nt]);
        mma_bf16(acc[mt][nt], ah[mt], bl[nt]);
        mma_bf16(acc[mt][nt], al[mt], bh[nt]);
      }
  }

  // ---- epilogue: d0,d1 at (row, col..col+1), d2,d3 at (row+8, ...) ----
  const int r0 = lane >> 2;
  const int cc = (lane & 3) * 2;
  #pragma unroll
  for(int mt=0;mt<2;++mt){
    #pragma unroll
    for(int nt=0;nt<4;++nt){
      int col  = wn + nt*8 + cc;
      int row1 = e0 + wm + mt*16 + r0;
      if(row1 < EDGES){
        float2 v01 = make_float2(acc[mt][nt][0], acc[mt][nt][1]);
        *reinterpret_cast<float2*>(C + (size_t)row1*F + col) = v01;
      }
      int row2 = row1 + 8;
      if(row2 < EDGES){
        float2 v23 = make_float2(acc[mt][nt][2], acc[mt][nt][3]);
        *reinterpret_cast<float2*>(C + (size_t)row2*F + col) = v23;
      }
    }
  }
}

// ============================================================================
// Kernel 4: CG tensor product, template-unrolled with literal indices.
// ============================================================================
template<int Lo, int Hi, int L3SQ>
__device__ __forceinline__ void ent_run(const float* __restrict__ u,
                                        const float* __restrict__ v,
                                        float* __restrict__ praw)
{
  if constexpr (Hi - Lo == 1) {
    constexpr int i1 = cgbuild::CG.e[Lo].i1;
    constexpr int i2 = cgbuild::CG.e[Lo].i2;
    constexpr int i3 = cgbuild::CG.e[Lo].i3 - L3SQ;
    constexpr float c = cgbuild::CG.e[Lo].c;
    praw[i3] = fmaf(u[i1]*v[i2], c, praw[i3]);
  } else if constexpr (Hi > Lo) {
    constexpr int Mid = Lo + (Hi - Lo)/2;
    ent_run<Lo, Mid, L3SQ>(u, v, praw);
    ent_run<Mid, Hi, L3SQ>(u, v, praw);
  }
}

template<int P>
__device__ __forceinline__ void path_run(const float* __restrict__ u,
                                         const float* __restrict__ v,
                                         float* __restrict__ t,
                                         const float* __restrict__ wp, int f)
{
  if constexpr (P < 42) {
    constexpr int l3 = cgbuild::CG.pl3[P];
    constexpr int s  = cgbuild::CG.pstart[P];
    constexpr int e  = cgbuild::CG.pstart[P+1];
    float wpf = wp[P*64 + f];
    float praw[2*l3+1];
    #pragma unroll
    for(int c=0;c<2*l3+1;++c) praw[c] = 0.f;
    ent_run<s, e, l3*l3>(u, v, praw);
    #pragma unroll
    for(int c=0;c<2*l3+1;++c)
      t[l3*l3+c] = fmaf(praw[c], wpf, t[l3*l3+c]);
    path_run<P+1>(u, v, t, wp, f);
  }
}

__global__ void __launch_bounds__(128) k_cg(
    const float* __restrict__ u_, const float* __restrict__ v_,
    const float* __restrict__ wp, float* __restrict__ t_)
{
  int t = blockIdx.x*128 + threadIdx.x;
  if(t >= EDGES*F) return;
  int f = t & 63;

  float u[NLM], v[NLM], tacc[NLM];
  #pragma unroll
  for(int lm=0;lm<NLM;++lm){
    u[lm] = u_[(size_t)lm*EF + t];
    v[lm] = v_[(size_t)lm*EF + t];
    tacc[lm] = 0.f;
  }

  path_run<0>(u, v, tacc, wp, f);

  #pragma unroll
  for(int lm=0;lm<NLM;++lm) t_[(size_t)lm*EF + t] = tacc[lm];
}

// ============================================================================
// Kernel 5: scale + scatter-add to atoms
// ============================================================================
__global__ void __launch_bounds__(256) k_scatter(
    const float* __restrict__ y, const float* __restrict__ a,
    const int* __restrict__ nbr, const float* __restrict__ twt,
    float* __restrict__ out)
{
  int t = blockIdx.x*256 + threadIdx.x;
  int e = t>>6, f = t&63;
  if(e >= EDGES) return;
  int i = nbr[2*e];
  float af = a[(size_t)i*F + f];
  float* orow = out + (size_t)i*NLM*F + f;
  #pragma unroll
  for(int lm=0;lm<NLM;++lm){
    float val = y[(size_t)lm*EF + t] * af * twt[DEGC[lm]*F + f];
    atomicAdd(&orow[(size_t)lm*F], val);
  }
}

// ============================================================================
// Launch
// ============================================================================
extern "C" void kernel_launch(void* const* d_in, const int* in_sizes, int n_in,
                              void* d_out, int out_size)
{
  const int*   Z     = (const int*)  d_in[0];
  const int*   nbr   = (const int*)  d_in[1];
  const float* disp  = (const float*)d_in[2];
  const float* emb   = (const float*)d_in[3];
  const float* Wembt = (const float*)d_in[4];
  const float* Wrad  = (const float*)d_in[5];
  const float* W1[2] = { (const float*)d_in[6],  (const float*)d_in[10] };
  const float* W2[2] = { (const float*)d_in[7],  (const float*)d_in[11] };
  const float* wp[2] = { (const float*)d_in[8],  (const float*)d_in[12] };
  const float* Wo[2] = { (const float*)d_in[9],  (const float*)d_in[13] };
  const float* twt   = (const float*)d_in[14];
  float* out = (float*)d_out;

  float *y, *u, *v, *t, *a;
  cudaGetSymbolAddress((void**)&y, g_y);
  cudaGetSymbolAddress((void**)&u, g_u);
  cudaGetSymbolAddress((void**)&v, g_v);
  cudaGetSymbolAddress((void**)&t, g_t);
  cudaGetSymbolAddress((void**)&a, g_a);

  k_atom_emb<<<(ATOMS*F + 255)/256, 256>>>(Z, emb, Wembt, a, out);
  k_edge_y<<<(EDGES*F + 255)/256, 256>>>(nbr, disp, Z, Wrad, y);

  dim3 gg((EDGES + 127)/128, NLM);
  for(int L=0; L<2; ++L){
    k_gemm_mma<<<gg, 256>>>(y, W1[L], u);
    k_gemm_mma<<<gg, 256>>>(y, W2[L], v);
    k_cg<<<(EDGES*F + 127)/128, 128>>>(u, v, wp[L], t);
    k_gemm_mma<<<gg, 256>>>(t, Wo[L], y);
  }

  k_scatter<<<(EDGES*F + 255)/256, 256>>>(y, a, nbr, twt, out);
}

// round 13
// speedup vs baseline: 2.1042x; 1.3111x over previous
#include <cuda_runtime.h>
#include <cuda_bf16.h>
#include <math.h>
#include <stdint.h>

#define EDGES 40000
#define ATOMS 2000
#define F 64
#define NLM 25
#define EF ((size_t)EDGES * F)

// ============================================================================
// Compile-time real Clebsch-Gordan table (replicates reference exactly)
// ============================================================================
namespace cgbuild {

constexpr double cfact(int n){ double r=1.0; for(int i=2;i<=n;++i) r*=(double)i; return r; }
constexpr double csqrt(double v){
  if(v<=0.0) return 0.0;
  double x = v>1.0 ? v : 1.0;
  for(int i=0;i<64;++i) x = 0.5*(x + v/x);
  return x;
}
constexpr double cabsd(double v){ return v<0.0 ? -v : v; }

constexpr double cg_complex(int l1,int m1,int l2,int m2,int l3,int m3){
  if(m3 != m1+m2) return 0.0;
  int lmin = l1>l2 ? l1-l2 : l2-l1;
  if(l3 < lmin || l3 > l1+l2) return 0.0;
  double pre = (2.0*l3+1.0)*cfact(l1+l2-l3)*cfact(l1-l2+l3)*cfact(-l1+l2+l3)/cfact(l1+l2+l3+1);
  pre = csqrt(pre*cfact(l1+m1)*cfact(l1-m1)*cfact(l2+m2)*cfact(l2-m2)*cfact(l3+m3)*cfact(l3-m3));
  double s = 0.0;
  for(int k=0;k<=l1+l2-l3;++k){
    int d2=l1-m1-k, d3=l2+m2-k, d4=l3-l2+m1+k, d5=l3-l1-m2+k;
    if(d2<0||d3<0||d4<0||d5<0) continue;
    double den = cfact(k)*cfact(l1+l2-l3-k)*cfact(d2)*cfact(d3)*cfact(d4)*cfact(d5);
    s += ((k&1) ? -1.0 : 1.0)/den;
  }
  return pre*s;
}

struct CD { double re, im; };
constexpr CD cmul(CD a, CD b){ return CD{a.re*b.re - a.im*b.im, a.re*b.im + a.im*b.re}; }

constexpr double INV_SQRT2 = 0.70710678118654752440;

struct URow { int n; int m[2]; CD c[2]; };
constexpr URow urow(int l, int a){
  URow r{};
  int m = a - l;
  double s = INV_SQRT2;
  if(m==0){ r.n=1; r.m[0]=0; r.c[0]=CD{1.0,0.0}; return r; }
  if(m>0){
    r.n=2;
    r.m[0]=m;  r.c[0]=CD{ ((m&1)? -1.0:1.0)*s, 0.0};
    r.m[1]=-m; r.c[1]=CD{ s, 0.0};
    return r;
  }
  int am = -m;
  r.n=2;
  r.m[0]=m;  r.c[0]=CD{0.0, s};
  r.m[1]=am; r.c[1]=CD{0.0, -(((am&1)? -1.0:1.0))*s};
  return r;
}

constexpr int MAXE = 4608;
struct Ent { int i1,i2,i3; float c; };
struct CGTab {
  Ent e[MAXE];
  int pstart[43];
  int pl3[42];
  int n; int npaths; bool overflow;
};

constexpr CGTab build_cg(){
  CGTab T{};
  int p = 0;
  for(int l1=0;l1<=4;++l1)
  for(int l2=0;l2<=4;++l2){
    int lmin = l1>l2 ? l1-l2 : l2-l1;
    int lcap = (l1+l2 < 4) ? (l1+l2) : 4;
    for(int l3=lmin; l3<=lcap; ++l3){
      if(((l1+l2+l3)&1) != 0) continue;
      T.pstart[p] = T.n;
      T.pl3[p] = l3;
      for(int a=0;a<2*l1+1;++a)
      for(int b=0;b<2*l2+1;++b){
        double acc[9]={0,0,0,0,0,0,0,0,0};
        URow u1 = urow(l1,a);
        URow u2 = urow(l2,b);
        for(int t1=0;t1<u1.n;++t1)
        for(int t2=0;t2<u2.n;++t2){
          int m3 = u1.m[t1]+u2.m[t2];
          if(m3 > l3 || m3 < -l3) continue;
          double cc = cg_complex(l1,u1.m[t1],l2,u2.m[t2],l3,m3);
          if(cc==0.0) continue;
          CD c12 = cmul(u1.c[t1], u2.c[t2]);
          c12.re *= cc; c12.im *= cc;
          int rows[2] = { m3, -m3 };
          int nr = (m3==0) ? 1 : 2;
          for(int rr=0;rr<nr;++rr){
            int cidx = rows[rr] + l3;
            URow u3 = urow(l3, cidx);
            for(int t3=0;t3<u3.n;++t3){
              if(u3.m[t3]==m3){
                acc[cidx] += c12.re*u3.c[t3].re + c12.im*u3.c[t3].im;
              }
            }
          }
        }
        for(int c_=0;c_<2*l3+1;++c_){
          if(cabsd(acc[c_]) > 1e-10){
            if(T.n >= MAXE){ T.overflow = true; }
            else {
              T.e[T.n].i1 = l1*l1 + a;
              T.e[T.n].i2 = l2*l2 + b;
              T.e[T.n].i3 = l3*l3 + c_;
              T.e[T.n].c  = (float)acc[c_];
              T.n++;
            }
          }
        }
      }
      ++p;
    }
  }
  T.pstart[p] = T.n;
  T.npaths = p;
  return T;
}

constexpr CGTab CG = build_cg();
static_assert(!CG.overflow, "cg table overflow");
static_assert(CG.npaths == 42, "path count must be 42");
static_assert(CG.n > 0, "cg table empty");

} // namespace cgbuild

// ============================================================================
// Scratch (device globals: sanctioned no-alloc workaround)
// ============================================================================
__device__ float g_y[NLM*(size_t)EDGES*F];
__device__ float g_u[NLM*(size_t)EDGES*F];
__device__ float g_v[NLM*(size_t)EDGES*F];
__device__ float g_t[NLM*(size_t)EDGES*F];
__device__ float g_a[(size_t)ATOMS*F];

__constant__ int DEGC[NLM] = {0,1,1,1,2,2,2,2,2,3,3,3,3,3,3,3,4,4,4,4,4,4,4,4,4};

// ============================================================================
// mma.sync / ldmatrix helpers (base ISA, works at compute_100 non-'a')
// ============================================================================
__device__ __forceinline__ uint32_t smem_u32(const void* p){
  uint32_t a;
  asm("{ .reg .u64 t; cvta.to.shared.u64 t, %1; cvt.u32.u64 %0, t; }" : "=r"(a) : "l"(p));
  return a;
}
__device__ __forceinline__ void ldsm_x4(uint32_t addr, uint32_t& r0, uint32_t& r1,
                                        uint32_t& r2, uint32_t& r3){
  asm volatile("ldmatrix.sync.aligned.m8n8.x4.shared.b16 {%0,%1,%2,%3}, [%4];"
    : "=r"(r0), "=r"(r1), "=r"(r2), "=r"(r3) : "r"(addr));
}
__device__ __forceinline__ void ldsm_x4_t(uint32_t addr, uint32_t& r0, uint32_t& r1,
                                          uint32_t& r2, uint32_t& r3){
  asm volatile("ldmatrix.sync.aligned.m8n8.x4.trans.shared.b16 {%0,%1,%2,%3}, [%4];"
    : "=r"(r0), "=r"(r1), "=r"(r2), "=r"(r3) : "r"(addr));
}
__device__ __forceinline__ void mma_bf16(float* d, const uint32_t* a, const uint32_t* b){
  asm volatile("mma.sync.aligned.m16n8k16.row.col.f32.bf16.bf16.f32 "
    "{%0,%1,%2,%3}, {%4,%5,%6,%7}, {%8,%9}, {%0,%1,%2,%3};"
    : "+f"(d[0]), "+f"(d[1]), "+f"(d[2]), "+f"(d[3])
    : "r"(a[0]), "r"(a[1]), "r"(a[2]), "r"(a[3]), "r"(b[0]), "r"(b[1]));
}
__device__ __forceinline__ void f4_split(float4 v, uint2& hp, uint2& lp){
  __nv_bfloat162 h01 = __floats2bfloat162_rn(v.x, v.y);
  __nv_bfloat162 h23 = __floats2bfloat162_rn(v.z, v.w);
  __nv_bfloat162 l01 = __floats2bfloat162_rn(v.x - __bfloat162float(h01.x),
                                             v.y - __bfloat162float(h01.y));
  __nv_bfloat162 l23 = __floats2bfloat162_rn(v.z - __bfloat162float(h23.x),
                                             v.w - __bfloat162float(h23.y));
  hp.x = *reinterpret_cast<uint32_t*>(&h01); hp.y = *reinterpret_cast<uint32_t*>(&h23);
  lp.x = *reinterpret_cast<uint32_t*>(&l01); lp.y = *reinterpret_cast<uint32_t*>(&l23);
}

// ============================================================================
// Kernel 1: per-atom embedding a = emb[Z] @ W_emb_t ; init d_out
// ============================================================================
__global__ void __launch_bounds__(256) k_atom_emb(
    const int* __restrict__ Z, const float* __restrict__ emb,
    const float* __restrict__ Wt, float* __restrict__ a, float* __restrict__ out)
{
  int t = blockIdx.x*256 + threadIdx.x;
  if(t >= ATOMS*F) return;
  int n = t>>6, f = t&63;
  int z = Z[n];
  const float* er = emb + (size_t)z*F;
  float s = 0.f;
  #pragma unroll
  for(int k=0;k<F;++k) s = fmaf(er[k], Wt[k*F+f], s);
  a[t] = s;
  float* orow = out + (size_t)n*NLM*F + f;
  orow[0] = s;
  #pragma unroll
  for(int lm=1;lm<NLM;++lm) orow[(size_t)lm*F] = 0.f;
}

// ============================================================================
// Kernel 2: edge features y[lm][e][f] = SH(unit)[lm] * rad[f]
// ============================================================================
__global__ void __launch_bounds__(256) k_edge_y(
    const int* __restrict__ nbr, const float* __restrict__ disp,
    const int* __restrict__ Z, const float* __restrict__ Wrad,
    float* __restrict__ y)
{
  int t = blockIdx.x*256 + threadIdx.x;
  int e = t>>6, f = t&63;
  if(e >= EDGES) return;
  int j  = nbr[2*e+1];
  int zj = Z[j];
  float dx = disp[3*e+0], dy = disp[3*e+1], dz = disp[3*e+2];
  float r = sqrtf(dx*dx + dy*dy + dz*dz + 1e-12f);
  float inv = 1.0f / r;
  float x = dx*inv, yy = dy*inv, z = dz*inv;
  float fc = 0.f;
  if(r < 5.0f) fc = 0.5f*(cosf(3.14159265358979323846f * r / 5.0f) + 1.0f);

  const float* wr = Wrad + (size_t)zj*16*F + f;
  float rad = 0.f;
  #pragma unroll
  for(int k=0;k<16;++k){
    float d = r - (float)k*(5.0f/15.0f);
    float g = expf(-10.24f*d*d)*fc;
    rad = fmaf(g, wr[(size_t)k*F], rad);
  }

  float x2=x*x, y2=yy*yy, z2=z*z;
  float sh[NLM];
  sh[0]=0.28209479177387814f;
  sh[1]=0.4886025119029199f*yy;
  sh[2]=0.4886025119029199f*z;
  sh[3]=0.4886025119029199f*x;
  sh[4]=1.0925484305920792f*x*yy;
  sh[5]=1.0925484305920792f*yy*z;
  sh[6]=0.31539156525252005f*(3.f*z2-1.f);
  sh[7]=1.0925484305920792f*x*z;
  sh[8]=0.5462742152960396f*(x2-y2);
  sh[9]=0.5900435899266435f*yy*(3.f*x2-y2);
  sh[10]=2.890611442640554f*x*yy*z;
  sh[11]=0.4570457994644658f*yy*(5.f*z2-1.f);
  sh[12]=0.3731763325901154f*z*(5.f*z2-3.f);
  sh[13]=0.4570457994644658f*x*(5.f*z2-1.f);
  sh[14]=1.445305721320277f*z*(x2-y2);
  sh[15]=0.5900435899266435f*x*(x2-3.f*y2);
  sh[16]=2.5033429417967046f*x*yy*(x2-y2);
  sh[17]=1.7701307697799304f*yy*z*(3.f*x2-y2);
  sh[18]=0.9461746957575601f*x*yy*(7.f*z2-1.f);
  sh[19]=0.6690465435572892f*yy*z*(7.f*z2-3.f);
  sh[20]=0.10578554691520431f*(35.f*z2*z2-30.f*z2+3.f);
  sh[21]=0.6690465435572892f*x*z*(7.f*z2-3.f);
  sh[22]=0.47308734787878004f*(x2-y2)*(7.f*z2-1.f);
  sh[23]=1.7701307697799304f*x*z*(x2-3.f*y2);
  sh[24]=0.6258357354491761f*(x2*x2-6.f*x2*y2+y2*y2);

  float* ye = y + (size_t)e*F + f;
  #pragma unroll
  for(int lm=0;lm<NLM;++lm) ye[(size_t)lm*EF] = sh[lm]*rad;
}

// ============================================================================
// GEMM building blocks (mma.sync bf16, 3xBF16 split).
// A tile: row-major [row][k] bf16, 16B chunks swizzled by (row&7).
// B tile: row-major [k][n]  bf16, 16B chunks swizzled by (k&7);
//         fragments via ldmatrix.x4.trans (canonical row-major-B pattern).
// Warp layout: 8 warps = 4(M) x 2(N), warp tile 32x32.
// ============================================================================

// Fill A hi/lo tiles (16KB each). 256 threads.
__device__ __forceinline__ void fill_A(const float* __restrict__ A, int e0,
                                       char* Ah, char* Al, int tid){
  #pragma unroll
  for(int i=0;i<8;++i){
    int idx = tid + 256*i;
    int row = idx >> 4, c4 = idx & 15;
    float4 v = make_float4(0.f,0.f,0.f,0.f);
    if(e0 + row < EDGES) v = reinterpret_cast<const float4*>(A + (size_t)(e0+row)*F)[c4];
    uint2 hp, lp; f4_split(v, hp, lp);
    int off = row*128 + (((c4>>1) ^ (row&7))<<4) + (c4&1)*8;
    *reinterpret_cast<uint2*>(Ah + off) = hp;
    *reinterpret_cast<uint2*>(Al + off) = lp;
  }
}

// Fill B hi/lo tiles (8KB each), row-major [k][n], vectorized. 256 threads.
__device__ __forceinline__ void fill_B(const float* __restrict__ B,
                                       char* Bh, char* Bl, int tid){
  #pragma unroll
  for(int i=0;i<4;++i){
    int idx = tid + 256*i;           // 1024 float4
    int k = idx >> 4, c4 = idx & 15; // n = c4*4..c4*4+3 consecutive
    float4 w = reinterpret_cast<const float4*>(B)[idx];
    uint2 hp, lp; f4_split(w, hp, lp);
    int off = k*128 + (((c4>>1) ^ (k&7))<<4) + (c4&1)*8;
    *reinterpret_cast<uint2*>(Bh + off) = hp;
    *reinterpret_cast<uint2*>(Bl + off) = lp;
  }
}

// Load B fragments for one kc: bh/bl[nt][2], nt=0..3 (warp N range wn..wn+31).
__device__ __forceinline__ void load_B_frags(uint32_t sBh, uint32_t sBl,
                                             int wn, int kc, int lane,
                                             uint32_t (&bh)[4][2], uint32_t (&bl)[4][2]){
  #pragma unroll
  for(int np=0;np<2;++np){
    int n0 = wn + np*16;
    int kk = kc*16 + (lane&7) + ((lane>>3)&1)*8;
    int noct = (n0>>3) + (lane>>4);
    uint32_t off = (uint32_t)(kk*128 + ((noct ^ (kk&7))<<4));
    uint32_t q0,q1,q2,q3;
    ldsm_x4_t(sBh + off, q0,q1,q2,q3);
    bh[np*2][0]=q0; bh[np*2][1]=q1; bh[np*2+1][0]=q2; bh[np*2+1][1]=q3;
    ldsm_x4_t(sBl + off, q0,q1,q2,q3);
    bl[np*2][0]=q0; bl[np*2][1]=q1; bl[np*2+1][0]=q2; bl[np*2+1][1]=q3;
  }
}

// Epilogue: write one warp's 32x32 fp32 result.
__device__ __forceinline__ void store_acc(float* __restrict__ C, int e0,
                                          int wm, int wn, int lane,
                                          const float (&acc)[2][4][4]){
  const int r0 = lane >> 2;
  const int cc = (lane & 3) * 2;
  #pragma unroll
  for(int mt=0;mt<2;++mt){
    #pragma unroll
    for(int nt=0;nt<4;++nt){
      int col  = wn + nt*8 + cc;
      int row1 = e0 + wm + mt*16 + r0;
      if(row1 < EDGES)
        *reinterpret_cast<float2*>(C + (size_t)row1*F + col) =
          make_float2(acc[mt][nt][0], acc[mt][nt][1]);
      int row2 = row1 + 8;
      if(row2 < EDGES)
        *reinterpret_cast<float2*>(C + (size_t)row2*F + col) =
          make_float2(acc[mt][nt][2], acc[mt][nt][3]);
    }
  }
}

// ---- single GEMM (Wout): dst = src @ W[deg]. 48KB static smem. ----
__global__ void __launch_bounds__(256) k_gemm_mma(
    const float* __restrict__ src, const float* __restrict__ W,
    float* __restrict__ dst)
{
  __shared__ __nv_bfloat16 Ah[128*64], Al[128*64];
  __shared__ __nv_bfloat16 Bh[64*64],  Bl[64*64];

  const int lm = blockIdx.y;
  const int e0 = blockIdx.x * 128;
  const float* A = src + (size_t)lm*EF;
  float*       C = dst + (size_t)lm*EF;
  const float* B = W + (size_t)DEGC[lm]*F*F;
  const int tid = threadIdx.x;

  fill_A(A, e0, reinterpret_cast<char*>(Ah), reinterpret_cast<char*>(Al), tid);
  fill_B(B, reinterpret_cast<char*>(Bh), reinterpret_cast<char*>(Bl), tid);
  __syncthreads();

  const int wid = tid >> 5, lane = tid & 31;
  const int wm = (wid >> 1) * 32;
  const int wn = (wid & 1) * 32;
  const int a_row0 = wm + (lane&7) + ((lane>>3)&1)*8;
  const int a_csel = lane >> 4;

  const uint32_t sAh = smem_u32(Ah), sAl = smem_u32(Al);
  const uint32_t sBh = smem_u32(Bh), sBl = smem_u32(Bl);

  float acc[2][4][4];
  #pragma unroll
  for(int mt=0;mt<2;++mt)
    #pragma unroll
    for(int nt=0;nt<4;++nt)
      #pragma unroll
      for(int q=0;q<4;++q) acc[mt][nt][q] = 0.f;

  #pragma unroll
  for(int kc=0;kc<4;++kc){
    uint32_t ah[2][4], al[2][4], bh[4][2], bl[4][2];
    #pragma unroll
    for(int mt=0;mt<2;++mt){
      int row = a_row0 + mt*16;
      uint32_t off = (uint32_t)(row*128 + (((2*kc + a_csel) ^ (row&7))<<4));
      ldsm_x4(sAh + off, ah[mt][0], ah[mt][1], ah[mt][2], ah[mt][3]);
      ldsm_x4(sAl + off, al[mt][0], al[mt][1], al[mt][2], al[mt][3]);
    }
    load_B_frags(sBh, sBl, wn, kc, lane, bh, bl);
    #pragma unroll
    for(int mt=0;mt<2;++mt)
      #pragma unroll
      for(int nt=0;nt<4;++nt){
        mma_bf16(acc[mt][nt], ah[mt], bh[nt]);
        mma_bf16(acc[mt][nt], ah[mt], bl[nt]);
        mma_bf16(acc[mt][nt], al[mt], bh[nt]);
      }
  }
  store_acc(C, e0, wm, wn, lane, acc);
}

// ---- fused dual GEMM: u = src@W1[deg], v = src@W2[deg]. 64KB dynamic smem. ----
__global__ void __launch_bounds__(256) k_gemm_uv(
    const float* __restrict__ src, const float* __restrict__ W1,
    const float* __restrict__ W2, float* __restrict__ dstU,
    float* __restrict__ dstV)
{
  extern __shared__ char S[];
  char* Ah  = S;            // 16KB
  char* Al  = S + 16384;    // 16KB
  char* B1h = S + 32768;    // 8KB
  char* B1l = S + 40960;
  char* B2h = S + 49152;
  char* B2l = S + 57344;

  const int lm = blockIdx.y;
  const int e0 = blockIdx.x * 128;
  const float* A  = src + (size_t)lm*EF;
  const float* B1 = W1 + (size_t)DEGC[lm]*F*F;
  const float* B2 = W2 + (size_t)DEGC[lm]*F*F;
  float* U = dstU + (size_t)lm*EF;
  float* V = dstV + (size_t)lm*EF;
  const int tid = threadIdx.x;

  fill_A(A, e0, Ah, Al, tid);
  fill_B(B1, B1h, B1l, tid);
  fill_B(B2, B2h, B2l, tid);
  __syncthreads();

  const int wid = tid >> 5, lane = tid & 31;
  const int wm = (wid >> 1) * 32;
  const int wn = (wid & 1) * 32;
  const int a_row0 = wm + (lane&7) + ((lane>>3)&1)*8;
  const int a_csel = lane >> 4;

  const uint32_t sAh = smem_u32(Ah), sAl = smem_u32(Al);
  const uint32_t sB1h = smem_u32(B1h), sB1l = smem_u32(B1l);
  const uint32_t sB2h = smem_u32(B2h), sB2l = smem_u32(B2l);

  float accU[2][4][4], accV[2][4][4];
  #pragma unroll
  for(int mt=0;mt<2;++mt)
    #pragma unroll
    for(int nt=0;nt<4;++nt)
      #pragma unroll
      for(int q=0;q<4;++q){ accU[mt][nt][q] = 0.f; accV[mt][nt][q] = 0.f; }

  #pragma unroll
  for(int kc=0;kc<4;++kc){
    uint32_t ah[2][4], al[2][4];
    #pragma unroll
    for(int mt=0;mt<2;++mt){
      int row = a_row0 + mt*16;
      uint32_t off = (uint32_t)(row*128 + (((2*kc + a_csel) ^ (row&7))<<4));
      ldsm_x4(sAh + off, ah[mt][0], ah[mt][1], ah[mt][2], ah[mt][3]);
      ldsm_x4(sAl + off, al[mt][0], al[mt][1], al[mt][2], al[mt][3]);
    }
    {
      uint32_t bh[4][2], bl[4][2];
      load_B_frags(sB1h, sB1l, wn, kc, lane, bh, bl);
      #pragma unroll
      for(int mt=0;mt<2;++mt)
        #pragma unroll
        for(int nt=0;nt<4;++nt){
          mma_bf16(accU[mt][nt], ah[mt], bh[nt]);
          mma_bf16(accU[mt][nt], ah[mt], bl[nt]);
          mma_bf16(accU[mt][nt], al[mt], bh[nt]);
        }
    }
    {
      uint32_t bh[4][2], bl[4][2];
      load_B_frags(sB2h, sB2l, wn, kc, lane, bh, bl);
      #pragma unroll
      for(int mt=0;mt<2;++mt)
        #pragma unroll
        for(int nt=0;nt<4;++nt){
          mma_bf16(accV[mt][nt], ah[mt], bh[nt]);
          mma_bf16(accV[mt][nt], ah[mt], bl[nt]);
          mma_bf16(accV[mt][nt], al[mt], bh[nt]);
        }
    }
  }
  store_acc(U, e0, wm, wn, lane, accU);
  store_acc(V, e0, wm, wn, lane, accV);
}

// ============================================================================
// Kernel 4: CG tensor product, template-unrolled with literal indices.
// ============================================================================
template<int Lo, int Hi, int L3SQ>
__device__ __forceinline__ void ent_run(const float* __restrict__ u,
                                        const float* __restrict__ v,
                                        float* __restrict__ praw)
{
  if constexpr (Hi - Lo == 1) {
    constexpr int i1 = cgbuild::CG.e[Lo].i1;
    constexpr int i2 = cgbuild::CG.e[Lo].i2;
    constexpr int i3 = cgbuild::CG.e[Lo].i3 - L3SQ;
    constexpr float c = cgbuild::CG.e[Lo].c;
    praw[i3] = fmaf(u[i1]*v[i2], c, praw[i3]);
  } else if constexpr (Hi > Lo) {
    constexpr int Mid = Lo + (Hi - Lo)/2;
    ent_run<Lo, Mid, L3SQ>(u, v, praw);
    ent_run<Mid, Hi, L3SQ>(u, v, praw);
  }
}

template<int P>
__device__ __forceinline__ void path_run(const float* __restrict__ u,
                                         const float* __restrict__ v,
                                         float* __restrict__ t,
                                         const float* __restrict__ wp, int f)
{
  if constexpr (P < 42) {
    constexpr int l3 = cgbuild::CG.pl3[P];
    constexpr int s  = cgbuild::CG.pstart[P];
    constexpr int e  = cgbuild::CG.pstart[P+1];
    float wpf = wp[P*64 + f];
    float praw[2*l3+1];
    #pragma unroll
    for(int c=0;c<2*l3+1;++c) praw[c] = 0.f;
    ent_run<s, e, l3*l3>(u, v, praw);
    #pragma unroll
    for(int c=0;c<2*l3+1;++c)
      t[l3*l3+c] = fmaf(praw[c], wpf, t[l3*l3+c]);
    path_run<P+1>(u, v, t, wp, f);
  }
}

__global__ void __launch_bounds__(128) k_cg(
    const float* __restrict__ u_, const float* __restrict__ v_,
    const float* __restrict__ wp, float* __restrict__ t_)
{
  int t = blockIdx.x*128 + threadIdx.x;
  if(t >= EDGES*F) return;
  int f = t & 63;

  float u[NLM], v[NLM], tacc[NLM];
  #pragma unroll
  for(int lm=0;lm<NLM;++lm){
    u[lm] = u_[(size_t)lm*EF + t];
    v[lm] = v_[(size_t)lm*EF + t];
    tacc[lm] = 0.f;
  }

  path_run<0>(u, v, tacc, wp, f);

  #pragma unroll
  for(int lm=0;lm<NLM;++lm) t_[(size_t)lm*EF + t] = tacc[lm];
}

// ============================================================================
// Kernel 5: scale + scatter-add to atoms
// ============================================================================
__global__ void __launch_bounds__(256) k_scatter(
    const float* __restrict__ y, const float* __restrict__ a,
    const int* __restrict__ nbr, const float* __restrict__ twt,
    float* __restrict__ out)
{
  int t = blockIdx.x*256 + threadIdx.x;
  int e = t>>6, f = t&63;
  if(e >= EDGES) return;
  int i = nbr[2*e];
  float af = a[(size_t)i*F + f];
  float* orow = out + (size_t)i*NLM*F + f;
  #pragma unroll
  for(int lm=0;lm<NLM;++lm){
    float val = y[(size_t)lm*EF + t] * af * twt[DEGC[lm]*F + f];
    atomicAdd(&orow[(size_t)lm*F], val);
  }
}

// ============================================================================
// Launch
// ============================================================================
extern "C" void kernel_launch(void* const* d_in, const int* in_sizes, int n_in,
                              void* d_out, int out_size)
{
  const int*   Z     = (const int*)  d_in[0];
  const int*   nbr   = (const int*)  d_in[1];
  const float* disp  = (const float*)d_in[2];
  const float* emb   = (const float*)d_in[3];
  const float* Wembt = (const float*)d_in[4];
  const float* Wrad  = (const float*)d_in[5];
  const float* W1[2] = { (const float*)d_in[6],  (const float*)d_in[10] };
  const float* W2[2] = { (const float*)d_in[7],  (const float*)d_in[11] };
  const float* wp[2] = { (const float*)d_in[8],  (const float*)d_in[12] };
  const float* Wo[2] = { (const float*)d_in[9],  (const float*)d_in[13] };
  const float* twt   = (const float*)d_in[14];
  float* out = (float*)d_out;

  float *y, *u, *v, *t, *a;
  cudaGetSymbolAddress((void**)&y, g_y);
  cudaGetSymbolAddress((void**)&u, g_u);
  cudaGetSymbolAddress((void**)&v, g_v);
  cudaGetSymbolAddress((void**)&t, g_t);
  cudaGetSymbolAddress((void**)&a, g_a);

  const int SMEM_UV = 65536;
  cudaFuncSetAttribute(k_gemm_uv, cudaFuncAttributeMaxDynamicSharedMemorySize, SMEM_UV);

  k_atom_emb<<<(ATOMS*F + 255)/256, 256>>>(Z, emb, Wembt, a, out);
  k_edge_y<<<(EDGES*F + 255)/256, 256>>>(nbr, disp, Z, Wrad, y);

  dim3 gg((EDGES + 127)/128, NLM);
  for(int L=0; L<2; ++L){
    k_gemm_uv<<<gg, 256, SMEM_UV>>>(y, W1[L], W2[L], u, v);
    k_cg<<<(EDGES*F + 127)/128, 128>>>(u, v, wp[L], t);
    k_gemm_mma<<<gg, 256>>>(t, Wo[L], y);
  }

  k_scatter<<<(EDGES*F + 255)/256, 256>>>(y, a, nbr, twt, out);
}

// round 14
// speedup vs baseline: 2.1254x; 1.0101x over previous
#include <cuda_runtime.h>
#include <cuda_bf16.h>
#include <math.h>
#include <stdint.h>

#define EDGES 40000
#define ATOMS 2000
#define F 64
#define NLM 25
#define EF ((size_t)EDGES * F)

// ============================================================================
// Compile-time real Clebsch-Gordan table (replicates reference exactly)
// ============================================================================
namespace cgbuild {

constexpr double cfact(int n){ double r=1.0; for(int i=2;i<=n;++i) r*=(double)i; return r; }
constexpr double csqrt(double v){
  if(v<=0.0) return 0.0;
  double x = v>1.0 ? v : 1.0;
  for(int i=0;i<64;++i) x = 0.5*(x + v/x);
  return x;
}
constexpr double cabsd(double v){ return v<0.0 ? -v : v; }

constexpr double cg_complex(int l1,int m1,int l2,int m2,int l3,int m3){
  if(m3 != m1+m2) return 0.0;
  int lmin = l1>l2 ? l1-l2 : l2-l1;
  if(l3 < lmin || l3 > l1+l2) return 0.0;
  double pre = (2.0*l3+1.0)*cfact(l1+l2-l3)*cfact(l1-l2+l3)*cfact(-l1+l2+l3)/cfact(l1+l2+l3+1);
  pre = csqrt(pre*cfact(l1+m1)*cfact(l1-m1)*cfact(l2+m2)*cfact(l2-m2)*cfact(l3+m3)*cfact(l3-m3));
  double s = 0.0;
  for(int k=0;k<=l1+l2-l3;++k){
    int d2=l1-m1-k, d3=l2+m2-k, d4=l3-l2+m1+k, d5=l3-l1-m2+k;
    if(d2<0||d3<0||d4<0||d5<0) continue;
    double den = cfact(k)*cfact(l1+l2-l3-k)*cfact(d2)*cfact(d3)*cfact(d4)*cfact(d5);
    s += ((k&1) ? -1.0 : 1.0)/den;
  }
  return pre*s;
}

struct CD { double re, im; };
constexpr CD cmul(CD a, CD b){ return CD{a.re*b.re - a.im*b.im, a.re*b.im + a.im*b.re}; }

constexpr double INV_SQRT2 = 0.70710678118654752440;

struct URow { int n; int m[2]; CD c[2]; };
constexpr URow urow(int l, int a){
  URow r{};
  int m = a - l;
  double s = INV_SQRT2;
  if(m==0){ r.n=1; r.m[0]=0; r.c[0]=CD{1.0,0.0}; return r; }
  if(m>0){
    r.n=2;
    r.m[0]=m;  r.c[0]=CD{ ((m&1)? -1.0:1.0)*s, 0.0};
    r.m[1]=-m; r.c[1]=CD{ s, 0.0};
    return r;
  }
  int am = -m;
  r.n=2;
  r.m[0]=m;  r.c[0]=CD{0.0, s};
  r.m[1]=am; r.c[1]=CD{0.0, -(((am&1)? -1.0:1.0))*s};
  return r;
}

constexpr int MAXE = 4608;
struct Ent { int i1,i2,i3; float c; };
struct CGTab {
  Ent e[MAXE];
  int pstart[43];
  int pl3[42];
  int n; int npaths; bool overflow;
};

constexpr CGTab build_cg(){
  CGTab T{};
  int p = 0;
  for(int l1=0;l1<=4;++l1)
  for(int l2=0;l2<=4;++l2){
    int lmin = l1>l2 ? l1-l2 : l2-l1;
    int lcap = (l1+l2 < 4) ? (l1+l2) : 4;
    for(int l3=lmin; l3<=lcap; ++l3){
      if(((l1+l2+l3)&1) != 0) continue;
      T.pstart[p] = T.n;
      T.pl3[p] = l3;
      for(int a=0;a<2*l1+1;++a)
      for(int b=0;b<2*l2+1;++b){
        double acc[9]={0,0,0,0,0,0,0,0,0};
        URow u1 = urow(l1,a);
        URow u2 = urow(l2,b);
        for(int t1=0;t1<u1.n;++t1)
        for(int t2=0;t2<u2.n;++t2){
          int m3 = u1.m[t1]+u2.m[t2];
          if(m3 > l3 || m3 < -l3) continue;
          double cc = cg_complex(l1,u1.m[t1],l2,u2.m[t2],l3,m3);
          if(cc==0.0) continue;
          CD c12 = cmul(u1.c[t1], u2.c[t2]);
          c12.re *= cc; c12.im *= cc;
          int rows[2] = { m3, -m3 };
          int nr = (m3==0) ? 1 : 2;
          for(int rr=0;rr<nr;++rr){
            int cidx = rows[rr] + l3;
            URow u3 = urow(l3, cidx);
            for(int t3=0;t3<u3.n;++t3){
              if(u3.m[t3]==m3){
                acc[cidx] += c12.re*u3.c[t3].re + c12.im*u3.c[t3].im;
              }
            }
          }
        }
        for(int c_=0;c_<2*l3+1;++c_){
          if(cabsd(acc[c_]) > 1e-10){
            if(T.n >= MAXE){ T.overflow = true; }
            else {
              T.e[T.n].i1 = l1*l1 + a;
              T.e[T.n].i2 = l2*l2 + b;
              T.e[T.n].i3 = l3*l3 + c_;
              T.e[T.n].c  = (float)acc[c_];
              T.n++;
            }
          }
        }
      }
      ++p;
    }
  }
  T.pstart[p] = T.n;
  T.npaths = p;
  return T;
}

constexpr CGTab CG = build_cg();
static_assert(!CG.overflow, "cg table overflow");
static_assert(CG.npaths == 42, "path count must be 42");
static_assert(CG.n > 0, "cg table empty");

} // namespace cgbuild

// ============================================================================
// Scratch (device globals: sanctioned no-alloc workaround)
// ============================================================================
__device__ float g_y[NLM*(size_t)EDGES*F];
__device__ float g_u[NLM*(size_t)EDGES*F];
__device__ float g_v[NLM*(size_t)EDGES*F];
__device__ float g_t[NLM*(size_t)EDGES*F];
__device__ float g_a[(size_t)ATOMS*F];

__constant__ int DEGC[NLM] = {0,1,1,1,2,2,2,2,2,3,3,3,3,3,3,3,4,4,4,4,4,4,4,4,4};

// ============================================================================
// mma.sync / ldmatrix helpers (base ISA, works at compute_100 non-'a')
// ============================================================================
__device__ __forceinline__ uint32_t smem_u32(const void* p){
  uint32_t a;
  asm("{ .reg .u64 t; cvta.to.shared.u64 t, %1; cvt.u32.u64 %0, t; }" : "=r"(a) : "l"(p));
  return a;
}
__device__ __forceinline__ void ldsm_x4(uint32_t addr, uint32_t& r0, uint32_t& r1,
                                        uint32_t& r2, uint32_t& r3){
  asm volatile("ldmatrix.sync.aligned.m8n8.x4.shared.b16 {%0,%1,%2,%3}, [%4];"
    : "=r"(r0), "=r"(r1), "=r"(r2), "=r"(r3) : "r"(addr));
}
__device__ __forceinline__ void ldsm_x4_t(uint32_t addr, uint32_t& r0, uint32_t& r1,
                                          uint32_t& r2, uint32_t& r3){
  asm volatile("ldmatrix.sync.aligned.m8n8.x4.trans.shared.b16 {%0,%1,%2,%3}, [%4];"
    : "=r"(r0), "=r"(r1), "=r"(r2), "=r"(r3) : "r"(addr));
}
__device__ __forceinline__ void mma_bf16(float* d, const uint32_t* a, const uint32_t* b){
  asm volatile("mma.sync.aligned.m16n8k16.row.col.f32.bf16.bf16.f32 "
    "{%0,%1,%2,%3}, {%4,%5,%6,%7}, {%8,%9}, {%0,%1,%2,%3};"
    : "+f"(d[0]), "+f"(d[1]), "+f"(d[2]), "+f"(d[3])
    : "r"(a[0]), "r"(a[1]), "r"(a[2]), "r"(a[3]), "r"(b[0]), "r"(b[1]));
}
__device__ __forceinline__ void f4_split(float4 v, uint2& hp, uint2& lp){
  __nv_bfloat162 h01 = __floats2bfloat162_rn(v.x, v.y);
  __nv_bfloat162 h23 = __floats2bfloat162_rn(v.z, v.w);
  __nv_bfloat162 l01 = __floats2bfloat162_rn(v.x - __bfloat162float(h01.x),
                                             v.y - __bfloat162float(h01.y));
  __nv_bfloat162 l23 = __floats2bfloat162_rn(v.z - __bfloat162float(h23.x),
                                             v.w - __bfloat162float(h23.y));
  hp.x = *reinterpret_cast<uint32_t*>(&h01); hp.y = *reinterpret_cast<uint32_t*>(&h23);
  lp.x = *reinterpret_cast<uint32_t*>(&l01); lp.y = *reinterpret_cast<uint32_t*>(&l23);
}

// ============================================================================
// Kernel 1: per-atom embedding a = emb[Z] @ W_emb_t ; init d_out
// ============================================================================
__global__ void __launch_bounds__(256) k_atom_emb(
    const int* __restrict__ Z, const float* __restrict__ emb,
    const float* __restrict__ Wt, float* __restrict__ a, float* __restrict__ out)
{
  int t = blockIdx.x*256 + threadIdx.x;
  if(t >= ATOMS*F) return;
  int n = t>>6, f = t&63;
  int z = Z[n];
  const float* er = emb + (size_t)z*F;
  float s = 0.f;
  #pragma unroll
  for(int k=0;k<F;++k) s = fmaf(er[k], Wt[k*F+f], s);
  a[t] = s;
  float* orow = out + (size_t)n*NLM*F + f;
  orow[0] = s;
  #pragma unroll
  for(int lm=1;lm<NLM;++lm) orow[(size_t)lm*F] = 0.f;
}

// ============================================================================
// Kernel 2: edge features y[lm][e][f] = SH(unit)[lm] * rad[f]
// ============================================================================
__global__ void __launch_bounds__(256) k_edge_y(
    const int* __restrict__ nbr, const float* __restrict__ disp,
    const int* __restrict__ Z, const float* __restrict__ Wrad,
    float* __restrict__ y)
{
  int t = blockIdx.x*256 + threadIdx.x;
  int e = t>>6, f = t&63;
  if(e >= EDGES) return;
  int j  = nbr[2*e+1];
  int zj = Z[j];
  float dx = disp[3*e+0], dy = disp[3*e+1], dz = disp[3*e+2];
  float r = sqrtf(dx*dx + dy*dy + dz*dz + 1e-12f);
  float inv = 1.0f / r;
  float x = dx*inv, yy = dy*inv, z = dz*inv;
  float fc = 0.f;
  if(r < 5.0f) fc = 0.5f*(cosf(3.14159265358979323846f * r / 5.0f) + 1.0f);

  const float* wr = Wrad + (size_t)zj*16*F + f;
  float rad = 0.f;
  #pragma unroll
  for(int k=0;k<16;++k){
    float d = r - (float)k*(5.0f/15.0f);
    float g = expf(-10.24f*d*d)*fc;
    rad = fmaf(g, wr[(size_t)k*F], rad);
  }

  float x2=x*x, y2=yy*yy, z2=z*z;
  float sh[NLM];
  sh[0]=0.28209479177387814f;
  sh[1]=0.4886025119029199f*yy;
  sh[2]=0.4886025119029199f*z;
  sh[3]=0.4886025119029199f*x;
  sh[4]=1.0925484305920792f*x*yy;
  sh[5]=1.0925484305920792f*yy*z;
  sh[6]=0.31539156525252005f*(3.f*z2-1.f);
  sh[7]=1.0925484305920792f*x*z;
  sh[8]=0.5462742152960396f*(x2-y2);
  sh[9]=0.5900435899266435f*yy*(3.f*x2-y2);
  sh[10]=2.890611442640554f*x*yy*z;
  sh[11]=0.4570457994644658f*yy*(5.f*z2-1.f);
  sh[12]=0.3731763325901154f*z*(5.f*z2-3.f);
  sh[13]=0.4570457994644658f*x*(5.f*z2-1.f);
  sh[14]=1.445305721320277f*z*(x2-y2);
  sh[15]=0.5900435899266435f*x*(x2-3.f*y2);
  sh[16]=2.5033429417967046f*x*yy*(x2-y2);
  sh[17]=1.7701307697799304f*yy*z*(3.f*x2-y2);
  sh[18]=0.9461746957575601f*x*yy*(7.f*z2-1.f);
  sh[19]=0.6690465435572892f*yy*z*(7.f*z2-3.f);
  sh[20]=0.10578554691520431f*(35.f*z2*z2-30.f*z2+3.f);
  sh[21]=0.6690465435572892f*x*z*(7.f*z2-3.f);
  sh[22]=0.47308734787878004f*(x2-y2)*(7.f*z2-1.f);
  sh[23]=1.7701307697799304f*x*z*(x2-3.f*y2);
  sh[24]=0.6258357354491761f*(x2*x2-6.f*x2*y2+y2*y2);

  float* ye = y + (size_t)e*F + f;
  #pragma unroll
  for(int lm=0;lm<NLM;++lm) ye[(size_t)lm*EF] = sh[lm]*rad;
}

// ============================================================================
// GEMM building blocks (mma.sync bf16, 3xBF16 split).
// A tile: row-major [row][k] bf16, 16B chunks swizzled by (row&7).
// B tile: row-major [k][n]  bf16, 16B chunks swizzled by (k&7); ldmatrix.trans.
// Warp layout: 8 warps = 4(M) x 2(N), warp tile 32x32.
// ============================================================================
__device__ __forceinline__ void fill_A(const float* __restrict__ A, int e0,
                                       char* Ah, char* Al, int tid){
  #pragma unroll
  for(int i=0;i<8;++i){
    int idx = tid + 256*i;
    int row = idx >> 4, c4 = idx & 15;
    float4 v = make_float4(0.f,0.f,0.f,0.f);
    if(e0 + row < EDGES) v = reinterpret_cast<const float4*>(A + (size_t)(e0+row)*F)[c4];
    uint2 hp, lp; f4_split(v, hp, lp);
    int off = row*128 + (((c4>>1) ^ (row&7))<<4) + (c4&1)*8;
    *reinterpret_cast<uint2*>(Ah + off) = hp;
    *reinterpret_cast<uint2*>(Al + off) = lp;
  }
}

__device__ __forceinline__ void fill_B(const float* __restrict__ B,
                                       char* Bh, char* Bl, int tid){
  #pragma unroll
  for(int i=0;i<4;++i){
    int idx = tid + 256*i;
    int k = idx >> 4, c4 = idx & 15;
    float4 w = reinterpret_cast<const float4*>(B)[idx];
    uint2 hp, lp; f4_split(w, hp, lp);
    int off = k*128 + (((c4>>1) ^ (k&7))<<4) + (c4&1)*8;
    *reinterpret_cast<uint2*>(Bh + off) = hp;
    *reinterpret_cast<uint2*>(Bl + off) = lp;
  }
}

__device__ __forceinline__ void load_B_frags(uint32_t sBh, uint32_t sBl,
                                             int wn, int kc, int lane,
                                             uint32_t (&bh)[4][2], uint32_t (&bl)[4][2]){
  #pragma unroll
  for(int np=0;np<2;++np){
    int n0 = wn + np*16;
    int kk = kc*16 + (lane&7) + ((lane>>3)&1)*8;
    int noct = (n0>>3) + (lane>>4);
    uint32_t off = (uint32_t)(kk*128 + ((noct ^ (kk&7))<<4));
    uint32_t q0,q1,q2,q3;
    ldsm_x4_t(sBh + off, q0,q1,q2,q3);
    bh[np*2][0]=q0; bh[np*2][1]=q1; bh[np*2+1][0]=q2; bh[np*2+1][1]=q3;
    ldsm_x4_t(sBl + off, q0,q1,q2,q3);
    bl[np*2][0]=q0; bl[np*2][1]=q1; bl[np*2+1][0]=q2; bl[np*2+1][1]=q3;
  }
}

// mainloop: acc += A_tile @ B_tile (3xBF16 split)
__device__ __forceinline__ void gemm_loop(uint32_t sAh, uint32_t sAl,
                                          uint32_t sBh, uint32_t sBl,
                                          int a_row0, int a_csel, int wn, int lane,
                                          float (&acc)[2][4][4]){
  #pragma unroll
  for(int kc=0;kc<4;++kc){
    uint32_t ah[2][4], al[2][4], bh[4][2], bl[4][2];
    #pragma unroll
    for(int mt=0;mt<2;++mt){
      int row = a_row0 + mt*16;
      uint32_t off = (uint32_t)(row*128 + (((2*kc + a_csel) ^ (row&7))<<4));
      ldsm_x4(sAh + off, ah[mt][0], ah[mt][1], ah[mt][2], ah[mt][3]);
      ldsm_x4(sAl + off, al[mt][0], al[mt][1], al[mt][2], al[mt][3]);
    }
    load_B_frags(sBh, sBl, wn, kc, lane, bh, bl);
    #pragma unroll
    for(int mt=0;mt<2;++mt)
      #pragma unroll
      for(int nt=0;nt<4;++nt){
        mma_bf16(acc[mt][nt], ah[mt], bh[nt]);
        mma_bf16(acc[mt][nt], ah[mt], bl[nt]);
        mma_bf16(acc[mt][nt], al[mt], bh[nt]);
      }
  }
}

__device__ __forceinline__ void store_acc(float* __restrict__ C, int e0,
                                          int wm, int wn, int lane,
                                          const float (&acc)[2][4][4]){
  const int r0 = lane >> 2;
  const int cc = (lane & 3) * 2;
  #pragma unroll
  for(int mt=0;mt<2;++mt){
    #pragma unroll
    for(int nt=0;nt<4;++nt){
      int col  = wn + nt*8 + cc;
      int row1 = e0 + wm + mt*16 + r0;
      if(row1 < EDGES)
        *reinterpret_cast<float2*>(C + (size_t)row1*F + col) =
          make_float2(acc[mt][nt][0], acc[mt][nt][1]);
      int row2 = row1 + 8;
      if(row2 < EDGES)
        *reinterpret_cast<float2*>(C + (size_t)row2*F + col) =
          make_float2(acc[mt][nt][2], acc[mt][nt][3]);
    }
  }
}

// Store accumulator fragments into smem A-tile (bf16 hi/lo, swizzled layout).
__device__ __forceinline__ void store_acc_smem(char* Ah, char* Al,
                                               int wm, int wn, int lane,
                                               const float (&acc)[2][4][4]){
  const int r0 = lane >> 2;
  const int cc = (lane & 3) * 2;
  #pragma unroll
  for(int mt=0;mt<2;++mt)
    #pragma unroll
    for(int nt=0;nt<4;++nt){
      int col = wn + nt*8 + cc;
      int c4 = col >> 2;
      int inb = (c4&1)*8 + (col&3)*2;
      #pragma unroll
      for(int h=0;h<2;++h){
        int row = wm + mt*16 + r0 + h*8;
        float v0 = acc[mt][nt][h*2+0], v1 = acc[mt][nt][h*2+1];
        __nv_bfloat162 hp = __floats2bfloat162_rn(v0, v1);
        __nv_bfloat162 lp = __floats2bfloat162_rn(v0 - __bfloat162float(hp.x),
                                                  v1 - __bfloat162float(hp.y));
        int off = row*128 + (((c4>>1) ^ (row&7))<<4) + inb;
        *reinterpret_cast<uint32_t*>(Ah + off) = *reinterpret_cast<uint32_t*>(&hp);
        *reinterpret_cast<uint32_t*>(Al + off) = *reinterpret_cast<uint32_t*>(&lp);
      }
    }
}

// ---- single GEMM: dst = src @ W[deg]. 48KB static smem. ----
__global__ void __launch_bounds__(256) k_gemm_mma(
    const float* __restrict__ src, const float* __restrict__ W,
    float* __restrict__ dst)
{
  __shared__ __nv_bfloat16 Ah[128*64], Al[128*64];
  __shared__ __nv_bfloat16 Bh[64*64],  Bl[64*64];

  const int lm = blockIdx.y;
  const int e0 = blockIdx.x * 128;
  const int tid = threadIdx.x;

  fill_A(src + (size_t)lm*EF, e0, reinterpret_cast<char*>(Ah), reinterpret_cast<char*>(Al), tid);
  fill_B(W + (size_t)DEGC[lm]*F*F, reinterpret_cast<char*>(Bh), reinterpret_cast<char*>(Bl), tid);
  __syncthreads();

  const int wid = tid >> 5, lane = tid & 31;
  const int wm = (wid >> 1) * 32, wn = (wid & 1) * 32;
  const int a_row0 = wm + (lane&7) + ((lane>>3)&1)*8;
  const int a_csel = lane >> 4;

  float acc[2][4][4] = {};
  gemm_loop(smem_u32(Ah), smem_u32(Al), smem_u32(Bh), smem_u32(Bl),
            a_row0, a_csel, wn, lane, acc);
  store_acc(dst + (size_t)lm*EF, e0, wm, wn, lane, acc);
}

// ---- fused dual GEMM: u = src@W1[deg], v = src@W2[deg]. 64KB dynamic. ----
__global__ void __launch_bounds__(256) k_gemm_uv(
    const float* __restrict__ src, const float* __restrict__ W1,
    const float* __restrict__ W2, float* __restrict__ dstU,
    float* __restrict__ dstV)
{
  extern __shared__ char S[];
  char* Ah  = S;         char* Al  = S + 16384;
  char* B1h = S + 32768; char* B1l = S + 40960;
  char* B2h = S + 49152; char* B2l = S + 57344;

  const int lm = blockIdx.y;
  const int e0 = blockIdx.x * 128;
  const int tid = threadIdx.x;
  const int doff = DEGC[lm]*F*F;

  fill_A(src + (size_t)lm*EF, e0, Ah, Al, tid);
  fill_B(W1 + doff, B1h, B1l, tid);
  fill_B(W2 + doff, B2h, B2l, tid);
  __syncthreads();

  const int wid = tid >> 5, lane = tid & 31;
  const int wm = (wid >> 1) * 32, wn = (wid & 1) * 32;
  const int a_row0 = wm + (lane&7) + ((lane>>3)&1)*8;
  const int a_csel = lane >> 4;
  const uint32_t sAh = smem_u32(Ah), sAl = smem_u32(Al);

  float accU[2][4][4] = {};
  gemm_loop(sAh, sAl, smem_u32(B1h), smem_u32(B1l), a_row0, a_csel, wn, lane, accU);
  store_acc(dstU + (size_t)lm*EF, e0, wm, wn, lane, accU);

  float accV[2][4][4] = {};
  gemm_loop(sAh, sAl, smem_u32(B2h), smem_u32(B2l), a_row0, a_csel, wn, lane, accV);
  store_acc(dstV + (size_t)lm*EF, e0, wm, wn, lane, accV);
}

// ---- FUSED Wout + next-layer uv: y = t@Wo (kept in smem), u=y@W1n, v=y@W2n ----
__global__ void __launch_bounds__(256) k_wout_uv(
    const float* __restrict__ t, const float* __restrict__ Wo,
    const float* __restrict__ W1n, const float* __restrict__ W2n,
    float* __restrict__ dstU, float* __restrict__ dstV)
{
  extern __shared__ char S[];
  char* Ah  = S;         char* Al  = S + 16384;
  char* Boh = S + 32768; char* Bol = S + 40960;
  char* B1h = S + 49152; char* B1l = S + 57344;
  char* B2h = S + 65536; char* B2l = S + 73728;   // total 80KB

  const int lm = blockIdx.y;
  const int e0 = blockIdx.x * 128;
  const int tid = threadIdx.x;
  const int doff = DEGC[lm]*F*F;

  fill_A(t + (size_t)lm*EF, e0, Ah, Al, tid);
  fill_B(Wo + doff,  Boh, Bol, tid);
  fill_B(W1n + doff, B1h, B1l, tid);
  fill_B(W2n + doff, B2h, B2l, tid);
  __syncthreads();

  const int wid = tid >> 5, lane = tid & 31;
  const int wm = (wid >> 1) * 32, wn = (wid & 1) * 32;
  const int a_row0 = wm + (lane&7) + ((lane>>3)&1)*8;
  const int a_csel = lane >> 4;
  const uint32_t sAh = smem_u32(Ah), sAl = smem_u32(Al);

  // phase 1: y_tile = t @ Wo
  {
    float accO[2][4][4] = {};
    gemm_loop(sAh, sAl, smem_u32(Boh), smem_u32(Bol), a_row0, a_csel, wn, lane, accO);
    __syncthreads();                       // all reads of Ah/Al done
    store_acc_smem(Ah, Al, wm, wn, lane, accO);  // overwrite A tile with y
  }
  __syncthreads();

  // phase 2: u = y @ W1n ; v = y @ W2n
  float accU[2][4][4] = {};
  gemm_loop(sAh, sAl, smem_u32(B1h), smem_u32(B1l), a_row0, a_csel, wn, lane, accU);
  store_acc(dstU + (size_t)lm*EF, e0, wm, wn, lane, accU);

  float accV[2][4][4] = {};
  gemm_loop(sAh, sAl, smem_u32(B2h), smem_u32(B2l), a_row0, a_csel, wn, lane, accV);
  store_acc(dstV + (size_t)lm*EF, e0, wm, wn, lane, accV);
}

// ---- FUSED Wout + scale + scatter: y = t@Wo; out[i,lm] += y * a[i] * twt ----
__global__ void __launch_bounds__(256) k_wout_scatter(
    const float* __restrict__ t, const float* __restrict__ Wo,
    const float* __restrict__ a, const int* __restrict__ nbr,
    const float* __restrict__ twt, float* __restrict__ out)
{
  __shared__ __nv_bfloat16 Ah[128*64], Al[128*64];
  __shared__ __nv_bfloat16 Bh[64*64],  Bl[64*64];

  const int lm = blockIdx.y;
  const int deg = DEGC[lm];
  const int e0 = blockIdx.x * 128;
  const int tid = threadIdx.x;

  fill_A(t + (size_t)lm*EF, e0, reinterpret_cast<char*>(Ah), reinterpret_cast<char*>(Al), tid);
  fill_B(Wo + deg*F*F, reinterpret_cast<char*>(Bh), reinterpret_cast<char*>(Bl), tid);
  __syncthreads();

  const int wid = tid >> 5, lane = tid & 31;
  const int wm = (wid >> 1) * 32, wn = (wid & 1) * 32;
  const int a_row0 = wm + (lane&7) + ((lane>>3)&1)*8;
  const int a_csel = lane >> 4;

  float acc[2][4][4] = {};
  gemm_loop(smem_u32(Ah), smem_u32(Al), smem_u32(Bh), smem_u32(Bl),
            a_row0, a_csel, wn, lane, acc);

  // epilogue: scale by a[idx_i]*twt[deg] and atomicAdd to atoms
  const int r0 = lane >> 2;
  const int cc = (lane & 3) * 2;
  float tw[8];
  #pragma unroll
  for(int nt=0;nt<4;++nt){
    tw[nt*2+0] = twt[deg*F + wn + nt*8 + cc];
    tw[nt*2+1] = twt[deg*F + wn + nt*8 + cc + 1];
  }
  #pragma unroll
  for(int mt=0;mt<2;++mt)
    #pragma unroll
    for(int h=0;h<2;++h){
      int row = e0 + wm + mt*16 + r0 + h*8;
      if(row < EDGES){
        int i = nbr[2*row];
        const float* arow = a + (size_t)i*F;
        float* orow = out + (size_t)i*NLM*F + (size_t)lm*F;
        #pragma unroll
        for(int nt=0;nt<4;++nt){
          int col = wn + nt*8 + cc;
          atomicAdd(&orow[col],   acc[mt][nt][h*2+0] * arow[col]   * tw[nt*2+0]);
          atomicAdd(&orow[col+1], acc[mt][nt][h*2+1] * arow[col+1] * tw[nt*2+1]);
        }
      }
    }
}

// ============================================================================
// Kernel 4: CG tensor product, template-unrolled with literal indices.
// ============================================================================
template<int Lo, int Hi, int L3SQ>
__device__ __forceinline__ void ent_run(const float* __restrict__ u,
                                        const float* __restrict__ v,
                                        float* __restrict__ praw)
{
  if constexpr (Hi - Lo == 1) {
    constexpr int i1 = cgbuild::CG.e[Lo].i1;
    constexpr int i2 = cgbuild::CG.e[Lo].i2;
    constexpr int i3 = cgbuild::CG.e[Lo].i3 - L3SQ;
    constexpr float c = cgbuild::CG.e[Lo].c;
    praw[i3] = fmaf(u[i1]*v[i2], c, praw[i3]);
  } else if constexpr (Hi > Lo) {
    constexpr int Mid = Lo + (Hi - Lo)/2;
    ent_run<Lo, Mid, L3SQ>(u, v, praw);
    ent_run<Mid, Hi, L3SQ>(u, v, praw);
  }
}

template<int P>
__device__ __forceinline__ void path_run(const float* __restrict__ u,
                                         const float* __restrict__ v,
                                         float* __restrict__ t,
                                         const float* __restrict__ wp, int f)
{
  if constexpr (P < 42) {
    constexpr int l3 = cgbuild::CG.pl3[P];
    constexpr int s  = cgbuild::CG.pstart[P];
    constexpr int e  = cgbuild::CG.pstart[P+1];
    float wpf = wp[P*64 + f];
    float praw[2*l3+1];
    #pragma unroll
    for(int c=0;c<2*l3+1;++c) praw[c] = 0.f;
    ent_run<s, e, l3*l3>(u, v, praw);
    #pragma unroll
    for(int c=0;c<2*l3+1;++c)
      t[l3*l3+c] = fmaf(praw[c], wpf, t[l3*l3+c]);
    path_run<P+1>(u, v, t, wp, f);
  }
}

__global__ void __launch_bounds__(128) k_cg(
    const float* __restrict__ u_, const float* __restrict__ v_,
    const float* __restrict__ wp, float* __restrict__ t_)
{
  int t = blockIdx.x*128 + threadIdx.x;
  if(t >= EDGES*F) return;
  int f = t & 63;

  float u[NLM], v[NLM], tacc[NLM];
  #pragma unroll
  for(int lm=0;lm<NLM;++lm){
    u[lm] = u_[(size_t)lm*EF + t];
    v[lm] = v_[(size_t)lm*EF + t];
    tacc[lm] = 0.f;
  }

  path_run<0>(u, v, tacc, wp, f);

  #pragma unroll
  for(int lm=0;lm<NLM;++lm) t_[(size_t)lm*EF + t] = tacc[lm];
}

// ============================================================================
// Launch
// ============================================================================
extern "C" void kernel_launch(void* const* d_in, const int* in_sizes, int n_in,
                              void* d_out, int out_size)
{
  const int*   Z     = (const int*)  d_in[0];
  const int*   nbr   = (const int*)  d_in[1];
  const float* disp  = (const float*)d_in[2];
  const float* emb   = (const float*)d_in[3];
  const float* Wembt = (const float*)d_in[4];
  const float* Wrad  = (const float*)d_in[5];
  const float* W1[2] = { (const float*)d_in[6],  (const float*)d_in[10] };
  const float* W2[2] = { (const float*)d_in[7],  (const float*)d_in[11] };
  const float* wp[2] = { (const float*)d_in[8],  (const float*)d_in[12] };
  const float* Wo[2] = { (const float*)d_in[9],  (const float*)d_in[13] };
  const float* twt   = (const float*)d_in[14];
  float* out = (float*)d_out;

  float *y, *u, *v, *t, *a;
  cudaGetSymbolAddress((void**)&y, g_y);
  cudaGetSymbolAddress((void**)&u, g_u);
  cudaGetSymbolAddress((void**)&v, g_v);
  cudaGetSymbolAddress((void**)&t, g_t);
  cudaGetSymbolAddress((void**)&a, g_a);

  const int SMEM_UV = 65536;
  const int SMEM_WUV = 81920;
  cudaFuncSetAttribute(k_gemm_uv, cudaFuncAttributeMaxDynamicSharedMemorySize, SMEM_UV);
  cudaFuncSetAttribute(k_wout_uv, cudaFuncAttributeMaxDynamicSharedMemorySize, SMEM_WUV);

  k_atom_emb<<<(ATOMS*F + 255)/256, 256>>>(Z, emb, Wembt, a, out);
  k_edge_y<<<(EDGES*F + 255)/256, 256>>>(nbr, disp, Z, Wrad, y);

  dim3 gg((EDGES + 127)/128, NLM);
  // layer 0 uv
  k_gemm_uv<<<gg, 256, SMEM_UV>>>(y, W1[0], W2[0], u, v);
  k_cg<<<(EDGES*F + 127)/128, 128>>>(u, v, wp[0], t);
  // fused: Wout(L0) + uv(L1)
  k_wout_uv<<<gg, 256, SMEM_WUV>>>(t, Wo[0], W1[1], W2[1], u, v);
  k_cg<<<(EDGES*F + 127)/128, 128>>>(u, v, wp[1], t);
  // fused: Wout(L1) + scale + scatter
  k_wout_scatter<<<gg, 256>>>(t, Wo[1], a, nbr, twt, out);
}

// round 16
// speedup vs baseline: 2.5268x; 1.1889x over previous
#include <cuda_runtime.h>
#include <cuda_bf16.h>
#include <math.h>
#include <stdint.h>

#define EDGES 40000
#define ATOMS 2000
#define F 64
#define NLM 25
#define EF ((size_t)EDGES * F)

// ============================================================================
// Compile-time real Clebsch-Gordan table (replicates reference exactly)
// ============================================================================
namespace cgbuild {

constexpr double cfact(int n){ double r=1.0; for(int i=2;i<=n;++i) r*=(double)i; return r; }
constexpr double csqrt(double v){
  if(v<=0.0) return 0.0;
  double x = v>1.0 ? v : 1.0;
  for(int i=0;i<64;++i) x = 0.5*(x + v/x);
  return x;
}
constexpr double cabsd(double v){ return v<0.0 ? -v : v; }

constexpr double cg_complex(int l1,int m1,int l2,int m2,int l3,int m3){
  if(m3 != m1+m2) return 0.0;
  int lmin = l1>l2 ? l1-l2 : l2-l1;
  if(l3 < lmin || l3 > l1+l2) return 0.0;
  double pre = (2.0*l3+1.0)*cfact(l1+l2-l3)*cfact(l1-l2+l3)*cfact(-l1+l2+l3)/cfact(l1+l2+l3+1);
  pre = csqrt(pre*cfact(l1+m1)*cfact(l1-m1)*cfact(l2+m2)*cfact(l2-m2)*cfact(l3+m3)*cfact(l3-m3));
  double s = 0.0;
  for(int k=0;k<=l1+l2-l3;++k){
    int d2=l1-m1-k, d3=l2+m2-k, d4=l3-l2+m1+k, d5=l3-l1-m2+k;
    if(d2<0||d3<0||d4<0||d5<0) continue;
    double den = cfact(k)*cfact(l1+l2-l3-k)*cfact(d2)*cfact(d3)*cfact(d4)*cfact(d5);
    s += ((k&1) ? -1.0 : 1.0)/den;
  }
  return pre*s;
}

struct CD { double re, im; };
constexpr CD cmul(CD a, CD b){ return CD{a.re*b.re - a.im*b.im, a.re*b.im + a.im*b.re}; }

constexpr double INV_SQRT2 = 0.70710678118654752440;

struct URow { int n; int m[2]; CD c[2]; };
constexpr URow urow(int l, int a){
  URow r{};
  int m = a - l;
  double s = INV_SQRT2;
  if(m==0){ r.n=1; r.m[0]=0; r.c[0]=CD{1.0,0.0}; return r; }
  if(m>0){
    r.n=2;
    r.m[0]=m;  r.c[0]=CD{ ((m&1)? -1.0:1.0)*s, 0.0};
    r.m[1]=-m; r.c[1]=CD{ s, 0.0};
    return r;
  }
  int am = -m;
  r.n=2;
  r.m[0]=m;  r.c[0]=CD{0.0, s};
  r.m[1]=am; r.c[1]=CD{0.0, -(((am&1)? -1.0:1.0))*s};
  return r;
}

constexpr int MAXE = 4608;
struct Ent { int i1,i2,i3; float c; };
struct CGTab {
  Ent e[MAXE];
  int pstart[43];
  int pl3[42];
  int n; int npaths; bool overflow;
};

constexpr CGTab build_cg(){
  CGTab T{};
  int p = 0;
  for(int l1=0;l1<=4;++l1)
  for(int l2=0;l2<=4;++l2){
    int lmin = l1>l2 ? l1-l2 : l2-l1;
    int lcap = (l1+l2 < 4) ? (l1+l2) : 4;
    for(int l3=lmin; l3<=lcap; ++l3){
      if(((l1+l2+l3)&1) != 0) continue;
      T.pstart[p] = T.n;
      T.pl3[p] = l3;
      for(int a=0;a<2*l1+1;++a)
      for(int b=0;b<2*l2+1;++b){
        double acc[9]={0,0,0,0,0,0,0,0,0};
        URow u1 = urow(l1,a);
        URow u2 = urow(l2,b);
        for(int t1=0;t1<u1.n;++t1)
        for(int t2=0;t2<u2.n;++t2){
          int m3 = u1.m[t1]+u2.m[t2];
          if(m3 > l3 || m3 < -l3) continue;
          double cc = cg_complex(l1,u1.m[t1],l2,u2.m[t2],l3,m3);
          if(cc==0.0) continue;
          CD c12 = cmul(u1.c[t1], u2.c[t2]);
          c12.re *= cc; c12.im *= cc;
          int rows[2] = { m3, -m3 };
          int nr = (m3==0) ? 1 : 2;
          for(int rr=0;rr<nr;++rr){
            int cidx = rows[rr] + l3;
            URow u3 = urow(l3, cidx);
            for(int t3=0;t3<u3.n;++t3){
              if(u3.m[t3]==m3){
                acc[cidx] += c12.re*u3.c[t3].re + c12.im*u3.c[t3].im;
              }
            }
          }
        }
        for(int c_=0;c_<2*l3+1;++c_){
          if(cabsd(acc[c_]) > 1e-10){
            if(T.n >= MAXE){ T.overflow = true; }
            else {
              T.e[T.n].i1 = l1*l1 + a;
              T.e[T.n].i2 = l2*l2 + b;
              T.e[T.n].i3 = l3*l3 + c_;
              T.e[T.n].c  = (float)acc[c_];
              T.n++;
            }
          }
        }
      }
      ++p;
    }
  }
  T.pstart[p] = T.n;
  T.npaths = p;
  return T;
}

constexpr CGTab CG = build_cg();
static_assert(!CG.overflow, "cg table overflow");
static_assert(CG.npaths == 42, "path count must be 42");
static_assert(CG.n > 0, "cg table empty");

} // namespace cgbuild

__host__ __device__ constexpr int dega(int lm){
  return lm==0 ? 0 : (lm<4 ? 1 : (lm<9 ? 2 : (lm<16 ? 3 : 4)));
}

// ============================================================================
// Scratch (device globals: sanctioned no-alloc workaround)
// ============================================================================
__device__ float g_y[NLM*(size_t)EDGES*F];   // rad (E*64) lives in slice 0
__device__ float g_u[NLM*(size_t)EDGES*F];   // R1[5] slices, later u[25]
__device__ float g_v[NLM*(size_t)EDGES*F];   // R2[5] slices, later v[25]
__device__ float g_t[NLM*(size_t)EDGES*F];
__device__ float g_a[(size_t)ATOMS*F];

__constant__ int DEGC[NLM] = {0,1,1,1,2,2,2,2,2,3,3,3,3,3,3,3,4,4,4,4,4,4,4,4,4};

// ============================================================================
// mma.sync / ldmatrix helpers (base ISA, works at compute_100 non-'a')
// ============================================================================
__device__ __forceinline__ uint32_t smem_u32(const void* p){
  uint32_t a;
  asm("{ .reg .u64 t; cvta.to.shared.u64 t, %1; cvt.u32.u64 %0, t; }" : "=r"(a) : "l"(p));
  return a;
}
__device__ __forceinline__ void ldsm_x4(uint32_t addr, uint32_t& r0, uint32_t& r1,
                                        uint32_t& r2, uint32_t& r3){
  asm volatile("ldmatrix.sync.aligned.m8n8.x4.shared.b16 {%0,%1,%2,%3}, [%4];"
    : "=r"(r0), "=r"(r1), "=r"(r2), "=r"(r3) : "r"(addr));
}
__device__ __forceinline__ void ldsm_x4_t(uint32_t addr, uint32_t& r0, uint32_t& r1,
                                          uint32_t& r2, uint32_t& r3){
  asm volatile("ldmatrix.sync.aligned.m8n8.x4.trans.shared.b16 {%0,%1,%2,%3}, [%4];"
    : "=r"(r0), "=r"(r1), "=r"(r2), "=r"(r3) : "r"(addr));
}
__device__ __forceinline__ void mma_bf16(float* d, const uint32_t* a, const uint32_t* b){
  asm volatile("mma.sync.aligned.m16n8k16.row.col.f32.bf16.bf16.f32 "
    "{%0,%1,%2,%3}, {%4,%5,%6,%7}, {%8,%9}, {%0,%1,%2,%3};"
    : "+f"(d[0]), "+f"(d[1]), "+f"(d[2]), "+f"(d[3])
    : "r"(a[0]), "r"(a[1]), "r"(a[2]), "r"(a[3]), "r"(b[0]), "r"(b[1]));
}
__device__ __forceinline__ void f4_split(float4 v, uint2& hp, uint2& lp){
  __nv_bfloat162 h01 = __floats2bfloat162_rn(v.x, v.y);
  __nv_bfloat162 h23 = __floats2bfloat162_rn(v.z, v.w);
  __nv_bfloat162 l01 = __floats2bfloat162_rn(v.x - __bfloat162float(h01.x),
                                             v.y - __bfloat162float(h01.y));
  __nv_bfloat162 l23 = __floats2bfloat162_rn(v.z - __bfloat162float(h23.x),
                                             v.w - __bfloat162float(h23.y));
  hp.x = *reinterpret_cast<uint32_t*>(&h01); hp.y = *reinterpret_cast<uint32_t*>(&h23);
  lp.x = *reinterpret_cast<uint32_t*>(&l01); lp.y = *reinterpret_cast<uint32_t*>(&l23);
}

// ============================================================================
// Kernel 1: per-atom embedding a = emb[Z] @ W_emb_t ; init d_out
// ============================================================================
__global__ void __launch_bounds__(256) k_atom_emb(
    const int* __restrict__ Z, const float* __restrict__ emb,
    const float* __restrict__ Wt, float* __restrict__ a, float* __restrict__ out)
{
  int t = blockIdx.x*256 + threadIdx.x;
  if(t >= ATOMS*F) return;
  int n = t>>6, f = t&63;
  int z = Z[n];
  const float* er = emb + (size_t)z*F;
  float s = 0.f;
  #pragma unroll
  for(int k=0;k<F;++k) s = fmaf(er[k], Wt[k*F+f], s);
  a[t] = s;
  float* orow = out + (size_t)n*NLM*F + f;
  orow[0] = s;
  #pragma unroll
  for(int lm=1;lm<NLM;++lm) orow[(size_t)lm*F] = 0.f;
}

// ============================================================================
// Kernel 2: radial features only: rad[e][f] (sh folded into k_cg_l0)
// ============================================================================
__global__ void __launch_bounds__(256) k_edge_rad(
    const int* __restrict__ nbr, const float* __restrict__ disp,
    const int* __restrict__ Z, const float* __restrict__ Wrad,
    float* __restrict__ rad)
{
  int t = blockIdx.x*256 + threadIdx.x;
  int e = t>>6, f = t&63;
  if(e >= EDGES) return;
  int j  = nbr[2*e+1];
  int zj = Z[j];
  float dx = disp[3*e+0], dy = disp[3*e+1], dz = disp[3*e+2];
  float r = sqrtf(dx*dx + dy*dy + dz*dz + 1e-12f);
  float fc = 0.f;
  if(r < 5.0f) fc = 0.5f*(cosf(3.14159265358979323846f * r / 5.0f) + 1.0f);

  const float* wr = Wrad + (size_t)zj*16*F + f;
  float acc = 0.f;
  #pragma unroll
  for(int k=0;k<16;++k){
    float d = r - (float)k*(5.0f/15.0f);
    float g = expf(-10.24f*d*d)*fc;
    acc = fmaf(g, wr[(size_t)k*F], acc);
  }
  rad[t] = acc;
}

// ============================================================================
// GEMM building blocks (mma.sync bf16, 3xBF16 split). (R14-proven)
// ============================================================================
__device__ __forceinline__ void fill_A(const float* __restrict__ A, int e0,
                                       char* Ah, char* Al, int tid){
  #pragma unroll
  for(int i=0;i<8;++i){
    int idx = tid + 256*i;
    int row = idx >> 4, c4 = idx & 15;
    float4 v = make_float4(0.f,0.f,0.f,0.f);
    if(e0 + row < EDGES) v = reinterpret_cast<const float4*>(A + (size_t)(e0+row)*F)[c4];
    uint2 hp, lp; f4_split(v, hp, lp);
    int off = row*128 + (((c4>>1) ^ (row&7))<<4) + (c4&1)*8;
    *reinterpret_cast<uint2*>(Ah + off) = hp;
    *reinterpret_cast<uint2*>(Al + off) = lp;
  }
}

__device__ __forceinline__ void fill_B(const float* __restrict__ B,
                                       char* Bh, char* Bl, int tid){
  #pragma unroll
  for(int i=0;i<4;++i){
    int idx = tid + 256*i;
    int k = idx >> 4, c4 = idx & 15;
    float4 w = reinterpret_cast<const float4*>(B)[idx];
    uint2 hp, lp; f4_split(w, hp, lp);
    int off = k*128 + (((c4>>1) ^ (k&7))<<4) + (c4&1)*8;
    *reinterpret_cast<uint2*>(Bh + off) = hp;
    *reinterpret_cast<uint2*>(Bl + off) = lp;
  }
}

__device__ __forceinline__ void load_B_frags(uint32_t sBh, uint32_t sBl,
                                             int wn, int kc, int lane,
                                             uint32_t (&bh)[4][2], uint32_t (&bl)[4][2]){
  #pragma unroll
  for(int np=0;np<2;++np){
    int n0 = wn + np*16;
    int kk = kc*16 + (lane&7) + ((lane>>3)&1)*8;
    int noct = (n0>>3) + (lane>>4);
    uint32_t off = (uint32_t)(kk*128 + ((noct ^ (kk&7))<<4));
    uint32_t q0,q1,q2,q3;
    ldsm_x4_t(sBh + off, q0,q1,q2,q3);
    bh[np*2][0]=q0; bh[np*2][1]=q1; bh[np*2+1][0]=q2; bh[np*2+1][1]=q3;
    ldsm_x4_t(sBl + off, q0,q1,q2,q3);
    bl[np*2][0]=q0; bl[np*2][1]=q1; bl[np*2+1][0]=q2; bl[np*2+1][1]=q3;
  }
}

__device__ __forceinline__ void gemm_loop(uint32_t sAh, uint32_t sAl,
                                          uint32_t sBh, uint32_t sBl,
                                          int a_row0, int a_csel, int wn, int lane,
                                          float (&acc)[2][4][4]){
  #pragma unroll
  for(int kc=0;kc<4;++kc){
    uint32_t ah[2][4], al[2][4], bh[4][2], bl[4][2];
    #pragma unroll
    for(int mt=0;mt<2;++mt){
      int row = a_row0 + mt*16;
      uint32_t off = (uint32_t)(row*128 + (((2*kc + a_csel) ^ (row&7))<<4));
      ldsm_x4(sAh + off, ah[mt][0], ah[mt][1], ah[mt][2], ah[mt][3]);
      ldsm_x4(sAl + off, al[mt][0], al[mt][1], al[mt][2], al[mt][3]);
    }
    load_B_frags(sBh, sBl, wn, kc, lane, bh, bl);
    #pragma unroll
    for(int mt=0;mt<2;++mt)
      #pragma unroll
      for(int nt=0;nt<4;++nt){
        mma_bf16(acc[mt][nt], ah[mt], bh[nt]);
        mma_bf16(acc[mt][nt], ah[mt], bl[nt]);
        mma_bf16(acc[mt][nt], al[mt], bh[nt]);
      }
  }
}

__device__ __forceinline__ void store_acc(float* __restrict__ C, int e0,
                                          int wm, int wn, int lane,
                                          const float (&acc)[2][4][4]){
  const int r0 = lane >> 2;
  const int cc = (lane & 3) * 2;
  #pragma unroll
  for(int mt=0;mt<2;++mt){
    #pragma unroll
    for(int nt=0;nt<4;++nt){
      int col  = wn + nt*8 + cc;
      int row1 = e0 + wm + mt*16 + r0;
      if(row1 < EDGES)
        *reinterpret_cast<float2*>(C + (size_t)row1*F + col) =
          make_float2(acc[mt][nt][0], acc[mt][nt][1]);
      int row2 = row1 + 8;
      if(row2 < EDGES)
        *reinterpret_cast<float2*>(C + (size_t)row2*F + col) =
          make_float2(acc[mt][nt][2], acc[mt][nt][3]);
    }
  }
}

__device__ __forceinline__ void store_acc_smem(char* Ah, char* Al,
                                               int wm, int wn, int lane,
                                               const float (&acc)[2][4][4]){
  const int r0 = lane >> 2;
  const int cc = (lane & 3) * 2;
  #pragma unroll
  for(int mt=0;mt<2;++mt)
    #pragma unroll
    for(int nt=0;nt<4;++nt){
      int col = wn + nt*8 + cc;
      int c4 = col >> 2;
      int inb = (c4&1)*8 + (col&3)*2;
      #pragma unroll
      for(int h=0;h<2;++h){
        int row = wm + mt*16 + r0 + h*8;
        float v0 = acc[mt][nt][h*2+0], v1 = acc[mt][nt][h*2+1];
        __nv_bfloat162 hp = __floats2bfloat162_rn(v0, v1);
        __nv_bfloat162 lp = __floats2bfloat162_rn(v0 - __bfloat162float(hp.x),
                                                  v1 - __bfloat162float(hp.y));
        int off = row*128 + (((c4>>1) ^ (row&7))<<4) + inb;
        *reinterpret_cast<uint32_t*>(Ah + off) = *reinterpret_cast<uint32_t*>(&hp);
        *reinterpret_cast<uint32_t*>(Al + off) = *reinterpret_cast<uint32_t*>(&lp);
      }
    }
}

// ---- layer-0 radial GEMMs: R1[d] = rad@W1[d], R2[d] = rad@W2[d], d=0..4 ----
__global__ void __launch_bounds__(256) k_gemm_r12(
    const float* __restrict__ rad, const float* __restrict__ W1,
    const float* __restrict__ W2, float* __restrict__ R1,
    float* __restrict__ R2)
{
  extern __shared__ char S[];
  char* Ah  = S;         char* Al  = S + 16384;
  char* B1h = S + 32768; char* B1l = S + 40960;
  char* B2h = S + 49152; char* B2l = S + 57344;

  const int d = blockIdx.y;
  const int e0 = blockIdx.x * 128;
  const int tid = threadIdx.x;
  const int doff = d*F*F;

  fill_A(rad, e0, Ah, Al, tid);
  fill_B(W1 + doff, B1h, B1l, tid);
  fill_B(W2 + doff, B2h, B2l, tid);
  __syncthreads();

  const int wid = tid >> 5, lane = tid & 31;
  const int wm = (wid >> 1) * 32, wn = (wid & 1) * 32;
  const int a_row0 = wm + (lane&7) + ((lane>>3)&1)*8;
  const int a_csel = lane >> 4;
  const uint32_t sAh = smem_u32(Ah), sAl = smem_u32(Al);

  float accU[2][4][4] = {};
  gemm_loop(sAh, sAl, smem_u32(B1h), smem_u32(B1l), a_row0, a_csel, wn, lane, accU);
  store_acc(R1 + (size_t)d*EF, e0, wm, wn, lane, accU);

  float accV[2][4][4] = {};
  gemm_loop(sAh, sAl, smem_u32(B2h), smem_u32(B2l), a_row0, a_csel, wn, lane, accV);
  store_acc(R2 + (size_t)d*EF, e0, wm, wn, lane, accV);
}

// ---- FUSED Wout + next-layer uv: y = t@Wo (kept in smem), u=y@W1n, v=y@W2n ----
__global__ void __launch_bounds__(256) k_wout_uv(
    const float* __restrict__ t, const float* __restrict__ Wo,
    const float* __restrict__ W1n, const float* __restrict__ W2n,
    float* __restrict__ dstU, float* __restrict__ dstV)
{
  extern __shared__ char S[];
  char* Ah  = S;         char* Al  = S + 16384;
  char* Boh = S + 32768; char* Bol = S + 40960;
  char* B1h = S + 49152; char* B1l = S + 57344;
  char* B2h = S + 65536; char* B2l = S + 73728;   // 80KB

  const int lm = blockIdx.y;
  const int e0 = blockIdx.x * 128;
  const int tid = threadIdx.x;
  const int doff = DEGC[lm]*F*F;

  fill_A(t + (size_t)lm*EF, e0, Ah, Al, tid);
  fill_B(Wo + doff,  Boh, Bol, tid);
  fill_B(W1n + doff, B1h, B1l, tid);
  fill_B(W2n + doff, B2h, B2l, tid);
  __syncthreads();

  const int wid = tid >> 5, lane = tid & 31;
  const int wm = (wid >> 1) * 32, wn = (wid & 1) * 32;
  const int a_row0 = wm + (lane&7) + ((lane>>3)&1)*8;
  const int a_csel = lane >> 4;
  const uint32_t sAh = smem_u32(Ah), sAl = smem_u32(Al);

  {
    float accO[2][4][4] = {};
    gemm_loop(sAh, sAl, smem_u32(Boh), smem_u32(Bol), a_row0, a_csel, wn, lane, accO);
    __syncthreads();
    store_acc_smem(Ah, Al, wm, wn, lane, accO);
  }
  __syncthreads();

  float accU[2][4][4] = {};
  gemm_loop(sAh, sAl, smem_u32(B1h), smem_u32(B1l), a_row0, a_csel, wn, lane, accU);
  store_acc(dstU + (size_t)lm*EF, e0, wm, wn, lane, accU);

  float accV[2][4][4] = {};
  gemm_loop(sAh, sAl, smem_u32(B2h), smem_u32(B2l), a_row0, a_csel, wn, lane, accV);
  store_acc(dstV + (size_t)lm*EF, e0, wm, wn, lane, accV);
}

// ---- FUSED Wout + scale + scatter ----
__global__ void __launch_bounds__(256) k_wout_scatter(
    const float* __restrict__ t, const float* __restrict__ Wo,
    const float* __restrict__ a, const int* __restrict__ nbr,
    const float* __restrict__ twt, float* __restrict__ out)
{
  __shared__ __nv_bfloat16 Ah[128*64], Al[128*64];
  __shared__ __nv_bfloat16 Bh[64*64],  Bl[64*64];

  const int lm = blockIdx.y;
  const int deg = DEGC[lm];
  const int e0 = blockIdx.x * 128;
  const int tid = threadIdx.x;

  fill_A(t + (size_t)lm*EF, e0, reinterpret_cast<char*>(Ah), reinterpret_cast<char*>(Al), tid);
  fill_B(Wo + deg*F*F, reinterpret_cast<char*>(Bh), reinterpret_cast<char*>(Bl), tid);
  __syncthreads();

  const int wid = tid >> 5, lane = tid & 31;
  const int wm = (wid >> 1) * 32, wn = (wid & 1) * 32;
  const int a_row0 = wm + (lane&7) + ((lane>>3)&1)*8;
  const int a_csel = lane >> 4;

  float acc[2][4][4] = {};
  gemm_loop(smem_u32(Ah), smem_u32(Al), smem_u32(Bh), smem_u32(Bl),
            a_row0, a_csel, wn, lane, acc);

  const int r0 = lane >> 2;
  const int cc = (lane & 3) * 2;
  float tw[8];
  #pragma unroll
  for(int nt=0;nt<4;++nt){
    tw[nt*2+0] = twt[deg*F + wn + nt*8 + cc];
    tw[nt*2+1] = twt[deg*F + wn + nt*8 + cc + 1];
  }
  #pragma unroll
  for(int mt=0;mt<2;++mt)
    #pragma unroll
    for(int h=0;h<2;++h){
      int row = e0 + wm + mt*16 + r0 + h*8;
      if(row < EDGES){
        int i = nbr[2*row];
        const float* arow = a + (size_t)i*F;
        float* orow = out + (size_t)i*NLM*F + (size_t)lm*F;
        #pragma unroll
        for(int nt=0;nt<4;++nt){
          int col = wn + nt*8 + cc;
          atomicAdd(&orow[col],   acc[mt][nt][h*2+0] * arow[col]   * tw[nt*2+0]);
          atomicAdd(&orow[col+1], acc[mt][nt][h*2+1] * arow[col+1] * tw[nt*2+1]);
        }
      }
    }
}

// ============================================================================
// CG tensor product chain (template-unrolled, literal indices)
// ============================================================================
template<int Lo, int Hi, int L3SQ>
__device__ __forceinline__ void ent_run(const float* __restrict__ u,
                                        const float* __restrict__ v,
                                        float* __restrict__ praw)
{
  if constexpr (Hi - Lo == 1) {
    constexpr int i1 = cgbuild::CG.e[Lo].i1;
    constexpr int i2 = cgbuild::CG.e[Lo].i2;
    constexpr int i3 = cgbuild::CG.e[Lo].i3 - L3SQ;
    constexpr float c = cgbuild::CG.e[Lo].c;
    praw[i3] = fmaf(u[i1]*v[i2], c, praw[i3]);
  } else if constexpr (Hi > Lo) {
    constexpr int Mid = Lo + (Hi - Lo)/2;
    ent_run<Lo, Mid, L3SQ>(u, v, praw);
    ent_run<Mid, Hi, L3SQ>(u, v, praw);
  }
}

template<int P>
__device__ __forceinline__ void path_run(const float* __restrict__ u,
                                         const float* __restrict__ v,
                                         float* __restrict__ t,
                                         const float* __restrict__ wp, int f)
{
  if constexpr (P < 42) {
    constexpr int l3 = cgbuild::CG.pl3[P];
    constexpr int s  = cgbuild::CG.pstart[P];
    constexpr int e  = cgbuild::CG.pstart[P+1];
    float wpf = wp[P*64 + f];
    float praw[2*l3+1];
    #pragma unroll
    for(int c=0;c<2*l3+1;++c) praw[c] = 0.f;
    ent_run<s, e, l3*l3>(u, v, praw);
    #pragma unroll
    for(int c=0;c<2*l3+1;++c)
      t[l3*l3+c] = fmaf(praw[c], wpf, t[l3*l3+c]);
    path_run<P+1>(u, v, t, wp, f);
  }
}

// ---- layer-1 CG (u, v materialized) ----
__global__ void __launch_bounds__(128) k_cg(
    const float* __restrict__ u_, const float* __restrict__ v_,
    const float* __restrict__ wp, float* __restrict__ t_)
{
  int t = blockIdx.x*128 + threadIdx.x;
  if(t >= EDGES*F) return;
  int f = t & 63;

  float u[NLM], v[NLM], tacc[NLM];
  #pragma unroll
  for(int lm=0;lm<NLM;++lm){
    u[lm] = u_[(size_t)lm*EF + t];
    v[lm] = v_[(size_t)lm*EF + t];
    tacc[lm] = 0.f;
  }

  path_run<0>(u, v, tacc, wp, f);

  #pragma unroll
  for(int lm=0;lm<NLM;++lm) t_[(size_t)lm*EF + t] = tacc[lm];
}

// ---- layer-0 CG: u/v reconstructed from rank-1 structure ----
// u[lm] = sh[lm](unit(e)) * R1[deg(lm)][e,f] ;  v likewise with R2.
__global__ void __launch_bounds__(128) k_cg_l0(
    const float* __restrict__ disp,
    const float* __restrict__ R1, const float* __restrict__ R2,
    const float* __restrict__ wp, float* __restrict__ t_)
{
  int t = blockIdx.x*128 + threadIdx.x;
  if(t >= EDGES*F) return;
  int e = t >> 6, f = t & 63;

  // unit vector (warp-uniform loads: lanes share e)
  float dx = disp[3*e+0], dy = disp[3*e+1], dz = disp[3*e+2];
  float r = sqrtf(dx*dx + dy*dy + dz*dz + 1e-12f);
  float inv = 1.0f / r;
  float x = dx*inv, yy = dy*inv, z = dz*inv;
  float x2=x*x, y2=yy*yy, z2=z*z;

  float sh[NLM];
  sh[0]=0.28209479177387814f;
  sh[1]=0.4886025119029199f*yy;
  sh[2]=0.4886025119029199f*z;
  sh[3]=0.4886025119029199f*x;
  sh[4]=1.0925484305920792f*x*yy;
  sh[5]=1.0925484305920792f*yy*z;
  sh[6]=0.31539156525252005f*(3.f*z2-1.f);
  sh[7]=1.0925484305920792f*x*z;
  sh[8]=0.5462742152960396f*(x2-y2);
  sh[9]=0.5900435899266435f*yy*(3.f*x2-y2);
  sh[10]=2.890611442640554f*x*yy*z;
  sh[11]=0.4570457994644658f*yy*(5.f*z2-1.f);
  sh[12]=0.3731763325901154f*z*(5.f*z2-3.f);
  sh[13]=0.4570457994644658f*x*(5.f*z2-1.f);
  sh[14]=1.445305721320277f*z*(x2-y2);
  sh[15]=0.5900435899266435f*x*(x2-3.f*y2);
  sh[16]=2.5033429417967046f*x*yy*(x2-y2);
  sh[17]=1.7701307697799304f*yy*z*(3.f*x2-y2);
  sh[18]=0.9461746957575601f*x*yy*(7.f*z2-1.f);
  sh[19]=0.6690465435572892f*yy*z*(7.f*z2-3.f);
  sh[20]=0.10578554691520431f*(35.f*z2*z2-30.f*z2+3.f);
  sh[21]=0.6690465435572892f*x*z*(7.f*z2-3.f);
  sh[22]=0.47308734787878004f*(x2-y2)*(7.f*z2-1.f);
  sh[23]=1.7701307697799304f*x*z*(x2-3.f*y2);
  sh[24]=0.6258357354491761f*(x2*x2-6.f*x2*y2+y2*y2);

  float r1[5], r2[5];
  #pragma unroll
  for(int d=0;d<5;++d){
    r1[d] = R1[(size_t)d*EF + t];
    r2[d] = R2[(size_t)d*EF + t];
  }

  float u[NLM], v[NLM], tacc[NLM];
  #pragma unroll
  for(int lm=0;lm<NLM;++lm){
    u[lm] = sh[lm]*r1[dega(lm)];
    v[lm] = sh[lm]*r2[dega(lm)];
    tacc[lm] = 0.f;
  }

  path_run<0>(u, v, tacc, wp, f);

  #pragma unroll
  for(int lm=0;lm<NLM;++lm) t_[(size_t)lm*EF + t] = tacc[lm];
}

// ============================================================================
// Launch
// ============================================================================
extern "C" void kernel_launch(void* const* d_in, const int* in_sizes, int n_in,
                              void* d_out, int out_size)
{
  const int*   Z     = (const int*)  d_in[0];
  const int*   nbr   = (const int*)  d_in[1];
  const float* disp  = (const float*)d_in[2];
  const float* emb   = (const float*)d_in[3];
  const float* Wembt = (const float*)d_in[4];
  const float* Wrad  = (const float*)d_in[5];
  const float* W1[2] = { (const float*)d_in[6],  (const float*)d_in[10] };
  const float* W2[2] = { (const float*)d_in[7],  (const float*)d_in[11] };
  const float* wp[2] = { (const float*)d_in[8],  (const float*)d_in[12] };
  const float* Wo[2] = { (const float*)d_in[9],  (const float*)d_in[13] };
  const float* twt   = (const float*)d_in[14];
  float* out = (float*)d_out;

  float *y, *u, *v, *t, *a;
  cudaGetSymbolAddress((void**)&y, g_y);
  cudaGetSymbolAddress((void**)&u, g_u);
  cudaGetSymbolAddress((void**)&v, g_v);
  cudaGetSymbolAddress((void**)&t, g_t);
  cudaGetSymbolAddress((void**)&a, g_a);

  const int SMEM_UV = 65536;
  const int SMEM_WUV = 81920;
  cudaFuncSetAttribute(k_gemm_r12, cudaFuncAttributeMaxDynamicSharedMemorySize, SMEM_UV);
  cudaFuncSetAttribute(k_wout_uv, cudaFuncAttributeMaxDynamicSharedMemorySize, SMEM_WUV);

  k_atom_emb<<<(ATOMS*F + 255)/256, 256>>>(Z, emb, Wembt, a, out);
  k_edge_rad<<<(EDGES*F + 255)/256, 256>>>(nbr, disp, Z, Wrad, y);

  dim3 gg((EDGES + 127)/128, NLM);
  dim3 g5((EDGES + 127)/128, 5);
  // layer 0: rank-1 factorization — 10 GEMM slices instead of 50
  k_gemm_r12<<<g5, 256, SMEM_UV>>>(y, W1[0], W2[0], u, v);
  k_cg_l0<<<(EDGES*F + 127)/128, 128>>>(disp, u, v, wp[0], t);
  // fused: Wout(L0) + uv(L1)
  k_wout_uv<<<gg, 256, SMEM_WUV>>>(t, Wo[0], W1[1], W2[1], u, v);
  k_cg<<<(EDGES*F + 127)/128, 128>>>(u, v, wp[1], t);
  // fused: Wout(L1) + scale + scatter
  k_wout_scatter<<<gg, 256>>>(t, Wo[1], a, nbr, twt, out);
}